// round 12
// baseline (speedup 1.0000x reference)
#include <cuda_runtime.h>
#include <cuda_bf16.h>
#include <cstdint>
#include <cmath>

#define HIDN 1024
#define EMBD 1024
#define BATCH 256
#define SEQL 128
#define NCLS 32000
#define NG   4096   /* 4*HIDN, gate-interleaved: n = 4*j + g */

#define BM 128
#define BN 64
#define BK 16
#define AS 20
#define BSS 20
#define GS 68
#define VSTR 516
#define ASTR 36
#define STG_A (128 * ASTR)
#define STG_U (64 * ASTR)

#define NCTA 128
#define PTHREADS 512   /* 8 recurrent warps + 8 input warps (warp-specialized) */

// fused kernel smem: V resident + h staging x2 + emb staging x2 + U staging x2
#define SMEM_P_BYTES ((64 * VSTR + 2 * STG_A + 2 * STG_A + 2 * STG_U) * 4)  /* 224256 */

// ---------------- device scratch (no allocations allowed) ----------------
static __device__ unsigned g_Ub[NG * (HIDN / 2)];            // 8 MB interleaved U, bf16x2
static __device__ unsigned g_Vb[NG * (HIDN / 2)];            // 8 MB interleaved V, bf16x2
static __device__ unsigned g_Eb[(size_t)NCLS * (EMBD / 2)];  // 64 MB emb, bf16x2
static __device__ float    g_ball[NG];
static __device__ float    g_zring[2][BATCH * NG];           // 32 MB z ring (2 steps)
static __device__ float    g_h[2][BATCH * HIDN];             // fp32 h (final proj reads [0])
static __device__ unsigned g_hb[2][BATCH * (HIDN / 2)];      // bf16x2 h ping-pong
static __device__ float    g_c[BATCH * HIDN];
static __device__ unsigned g_barA[32];                       // 2 barrier counters (slots 0,16)

// ---------------- helpers ----------------
__device__ __forceinline__ float f2tf32(float x) {
    uint32_t r;
    asm("cvt.rna.tf32.f32 %0, %1;" : "=r"(r) : "f"(x));
    return __uint_as_float(r);
}
__device__ __forceinline__ unsigned pack_bf2(float a, float b) {
    __nv_bfloat162 v = __floats2bfloat162_rn(a, b);
    return *reinterpret_cast<unsigned*>(&v);
}
__device__ __forceinline__ float fsig(float x) {
    return __fdividef(1.f, 1.f + __expf(-x));
}
__device__ __forceinline__ void mma_bf16(float* acc, const unsigned* a, const unsigned* b) {
    asm volatile(
        "mma.sync.aligned.m16n8k16.row.col.f32.bf16.bf16.f32 "
        "{%0,%1,%2,%3}, {%4,%5,%6,%7}, {%8,%9}, {%0,%1,%2,%3};"
        : "+f"(acc[0]), "+f"(acc[1]), "+f"(acc[2]), "+f"(acc[3])
        : "r"(a[0]), "r"(a[1]), "r"(a[2]), "r"(a[3]), "r"(b[0]), "r"(b[1]));
}
__device__ __forceinline__ uint32_t smem_u32(const void* p) {
    uint32_t a;
    asm("{ .reg .u64 t; cvta.to.shared.u64 t, %1; cvt.u32.u64 %0, t; }" : "=r"(a) : "l"(p));
    return a;
}
#define LDSM_X4(r0, r1, r2, r3, addr) \
    asm volatile("ldmatrix.sync.aligned.m8n8.x4.shared.b16 {%0,%1,%2,%3}, [%4];" \
                 : "=r"(r0), "=r"(r1), "=r"(r2), "=r"(r3) : "r"(addr))

// ---------------- pack: interleave U/V (bf16), biases, init state ----------------
__global__ void pack_kernel(const float* __restrict__ Ui, const float* __restrict__ Vi, const float* __restrict__ bi,
                            const float* __restrict__ Uf, const float* __restrict__ Vf, const float* __restrict__ bf,
                            const float* __restrict__ Uc, const float* __restrict__ Vc, const float* __restrict__ bc,
                            const float* __restrict__ Uo, const float* __restrict__ Vo, const float* __restrict__ bo,
                            const float* __restrict__ h0, const float* __restrict__ c0)
{
    int idx = blockIdx.x * blockDim.x + threadIdx.x;
    if (idx >= NG * (HIDN / 2)) return;
    if (idx < 32) g_barA[idx] = 0u;
    int n = idx >> 9;
    int k2 = idx & 511;
    int j = n >> 2, g = n & 3;
    const float *U, *V, *bb;
    if (g == 0)      { U = Ui; V = Vi; bb = bi; }
    else if (g == 1) { U = Uf; V = Vf; bb = bf; }
    else if (g == 2) { U = Uc; V = Vc; bb = bc; }
    else             { U = Uo; V = Vo; bb = bo; }
    const float* Up = U + (size_t)j * HIDN + 2 * k2;
    const float* Vp = V + (size_t)j * HIDN + 2 * k2;
    g_Ub[idx] = pack_bf2(Up[0], Up[1]);
    g_Vb[idx] = pack_bf2(Vp[0], Vp[1]);
    if (k2 == 0) g_ball[n] = bb[j];
    if (idx < BATCH * (HIDN / 2)) {
        g_hb[0][idx] = pack_bf2(h0[2 * idx], h0[2 * idx + 1]);
        float2 hv; hv.x = h0[2 * idx]; hv.y = h0[2 * idx + 1];
        *(float2*)&g_h[0][2 * idx] = hv;
        float2 cv; cv.x = c0[2 * idx]; cv.y = c0[2 * idx + 1];
        *(float2*)&g_c[2 * idx] = cv;
    }
}

__global__ void pack_emb_kernel(const float* __restrict__ emb)
{
    size_t idx = (size_t)blockIdx.x * blockDim.x + threadIdx.x;
    if (idx >= (size_t)NCLS * (EMBD / 2)) return;
    g_Eb[idx] = pack_bf2(emb[2 * idx], emb[2 * idx + 1]);
}

// ---------------- fused persistent kernel: warp-specialized steps + input GEMM ----------------
// 128 CTAs x 512 threads. Warps 0-7: recurrent GEMM (h[t] @ V^T, V resident, R10 structure).
// Warps 8-15: input GEMM for step t+1 (emb[X[:,t+1]] @ U^T), result to 2-slot global ring.
// Shared 16-chunk loop + syncs; epilogue (all 512 threads): gates = G + z(t) + bias, LSTM cell.
__global__ __launch_bounds__(PTHREADS, 1)
void lstm_fused_kernel(const int* __restrict__ Xids)
{
    extern __shared__ unsigned smem[];
    unsigned* smV = smem;                           // 64 x VSTR (resident V)
    unsigned* smH = smem + 64 * VSTR;               // 2 x STG_A (h staging)
    unsigned* smE = smH + 2 * STG_A;                // 2 x STG_A (emb staging)
    unsigned* smU = smE + 2 * STG_A;                // 2 x STG_U (U staging)
    float*    smG = (float*)smH;                    // G tile overlays h staging (epilogue)

    const int tid  = threadIdx.x;
    const int lane = tid & 31;
    const int bid = blockIdx.x;
    const int m0  = (bid & 1) * 128;
    const int nsl = bid >> 1;
    const int n0  = nsl * 64;
    unsigned* bar = &g_barA[(bid & 1) * 16];
    const bool isR = (tid < 256);                    // recurrent group

    // resident V slice (all threads)
    for (int i = tid; i < 64 * 128; i += PTHREADS) {
        int n = i >> 7, k4 = (i & 127) * 4;
        *(uint4*)&smV[n * VSTR + k4] = *(const uint4*)&g_Vb[(size_t)(n0 + n) * 512 + k4];
    }

    // c slice + bias (all threads; epilogue items: idx = tid + it*512, lr=idx>>3, jp=tid&7)
    const int zlr0 = tid >> 3, zjp = tid & 7;
    float creg[2][2];
#pragma unroll
    for (int it = 0; it < 2; it++) {
        float2 cv = *(const float2*)&g_c[(m0 + zlr0 + it * 64) * HIDN + nsl * 16 + zjp * 2];
        creg[it][0] = cv.x; creg[it][1] = cv.y;
    }
    float bb[8];
    {
        const float* bp = &g_ball[n0 + zjp * 8];
        float4 x0 = *(const float4*)bp;
        float4 x1 = *(const float4*)(bp + 4);
        bb[0] = x0.x; bb[1] = x0.y; bb[2] = x0.z; bb[3] = x0.w;
        bb[4] = x1.x; bb[5] = x1.y; bb[6] = x1.z; bb[7] = x1.w;
    }

    const uint32_t smH_u = smem_u32(smH);
    const uint32_t smV_u = smem_u32(smV);
    const uint32_t smE_u = smem_u32(smE);
    const uint32_t smU_u = smem_u32(smU);

    // ---- group-specific setup ----
    // recurrent (tids 0..255): warp gw 0..7, tile 32x32 over 128x64
    const int gw  = (tid >> 5) & 7;
    const int wm  = (gw >> 1) * 32;
    const int wn  = (gw & 1) * 32;
    uint32_t aoff[2], voff[2];
#pragma unroll
    for (int mt = 0; mt < 2; mt++)
        aoff[mt] = (uint32_t)(wm + mt * 16 + (lane & 7) + ((lane >> 3) & 1) * 8) * ASTR
                 + ((lane >> 4) & 1) * 4;
#pragma unroll
    for (int p = 0; p < 2; p++)
        voff[p] = (uint32_t)(wn + p * 16 + (lane & 7) + ((lane >> 4) & 1) * 8) * VSTR
                + ((lane >> 3) & 1) * 4;
    const int kcol  = (tid & 3) * 4;     // recurrent h staging
    const int ldrow = (tid & 255) >> 2;  // 0..63

    // input (tids 256..511): itid, warp tile 32x32 over 128x64 (same shape)
    const int itid = tid & 255;
    uint32_t eoff[2], uoff[2];
#pragma unroll
    for (int mt = 0; mt < 2; mt++)
        eoff[mt] = (uint32_t)(wm + mt * 16 + (lane & 7) + ((lane >> 3) & 1) * 8) * ASTR
                 + ((lane >> 4) & 1) * 4;
#pragma unroll
    for (int p = 0; p < 2; p++)
        uoff[p] = (uint32_t)(wn + p * 16 + (lane & 7) + ((lane >> 4) & 1) * 8) * ASTR
                + ((lane >> 3) & 1) * 4;
    // input staging maps: emb 128 rows x 8 16B-blocks = 1024 units / 256 thr = 4 each
    int erow[4]; uint32_t edst[4]; int ecb4[4];
#pragma unroll
    for (int i = 0; i < 4; i++) {
        int idx = itid + i * 256;
        erow[i] = idx >> 3;
        ecb4[i] = (idx & 7) * 4;
        edst[i] = (uint32_t)(erow[i] * ASTR + ecb4[i]);
    }
    // U 64 rows x 8 blocks = 512 units / 256 thr = 2 each (static across steps)
    const unsigned* usrc[2]; uint32_t udst[2];
#pragma unroll
    for (int i = 0; i < 2; i++) {
        int idx = itid + i * 256;
        int row = idx >> 3, cb4 = (idx & 7) * 4;
        usrc[i] = g_Ub + (size_t)(n0 + row) * 512 + cb4;
        udst[i] = (uint32_t)(row * ASTR + cb4);
    }

    __syncthreads();

    // t = -1: prologue (input warps compute z(0); recurrent idle through syncs)
    for (int t = -1; t < SEQL; t++) {
        const bool doR = (t >= 0);
        const int tn = (t + 1 < SEQL) ? (t + 1) : (SEQL - 1);

        // per-step global pointers
        const unsigned* hin = g_hb[t & 1];
        const unsigned* arp0 = hin + (size_t)(m0 + ldrow) * 512 + kcol;
        const unsigned* arp1 = hin + (size_t)(m0 + ldrow + 64) * 512 + kcol;
        const unsigned* esrc[4];
        if (!isR) {
#pragma unroll
            for (int i = 0; i < 4; i++) {
                int v = Xids[(m0 + erow[i]) * SEQL + tn];
                esrc[i] = g_Eb + (size_t)v * 512 + ecb4[i];
            }
        }

        float acc[2][4][4];
#pragma unroll
        for (int a = 0; a < 2; a++)
#pragma unroll
            for (int b_ = 0; b_ < 4; b_++)
#pragma unroll
                for (int c_ = 0; c_ < 4; c_++) acc[a][b_][c_] = 0.f;

        // stage chunk 0
        uint4 s0, s1, s2, s3;
        if (isR) {
            if (doR) {
                s0 = *(const uint4*)arp0;
                s1 = *(const uint4*)(arp0 + 16);
                s2 = *(const uint4*)arp1;
                s3 = *(const uint4*)(arp1 + 16);
                *(uint4*)&smH[ldrow * ASTR + kcol]             = s0;
                *(uint4*)&smH[ldrow * ASTR + kcol + 16]        = s1;
                *(uint4*)&smH[(ldrow + 64) * ASTR + kcol]      = s2;
                *(uint4*)&smH[(ldrow + 64) * ASTR + kcol + 16] = s3;
            }
        } else {
            s0 = *(const uint4*)esrc[0];
            s1 = *(const uint4*)esrc[1];
            s2 = *(const uint4*)esrc[2];
            s3 = *(const uint4*)esrc[3];
            uint4 u0 = *(const uint4*)usrc[0];
            uint4 u1 = *(const uint4*)usrc[1];
            *(uint4*)&smE[edst[0]] = s0;
            *(uint4*)&smE[edst[1]] = s1;
            *(uint4*)&smE[edst[2]] = s2;
            *(uint4*)&smE[edst[3]] = s3;
            *(uint4*)&smU[udst[0]] = u0;
            *(uint4*)&smU[udst[1]] = u1;
        }
        __syncthreads();

        // zpre prefetch for this step's epilogue (z(t) from ring; hidden behind GEMM)
        float4 zpre[2][2];
        if (doR) {
            const float* zr = g_zring[t & 1];
#pragma unroll
            for (int it = 0; it < 2; it++) {
                size_t zb = (size_t)(m0 + zlr0 + it * 64) * NG + n0 + zjp * 8;
                zpre[it][0] = *(const float4*)&zr[zb];
                zpre[it][1] = *(const float4*)&zr[zb + 4];
            }
        }

        for (int kc = 0; kc < 16; kc++) {
            const int cur = kc & 1;
            uint4 n0r, n1r, n2r, n3r, nu0, nu1;
            if (kc + 1 < 16) {
                if (isR) {
                    if (doR) {
                        n0r = *(const uint4*)(arp0 + (kc + 1) * 32);
                        n1r = *(const uint4*)(arp0 + (kc + 1) * 32 + 16);
                        n2r = *(const uint4*)(arp1 + (kc + 1) * 32);
                        n3r = *(const uint4*)(arp1 + (kc + 1) * 32 + 16);
                    }
                } else {
                    n0r = *(const uint4*)(esrc[0] + (kc + 1) * 32);
                    n1r = *(const uint4*)(esrc[1] + (kc + 1) * 32);
                    n2r = *(const uint4*)(esrc[2] + (kc + 1) * 32);
                    n3r = *(const uint4*)(esrc[3] + (kc + 1) * 32);
                    nu0 = *(const uint4*)(usrc[0] + (kc + 1) * 32);
                    nu1 = *(const uint4*)(usrc[1] + (kc + 1) * 32);
                }
            }

            if (isR) {
                if (doR) {
                    const uint32_t abase = smH_u + (uint32_t)cur * (STG_A * 4);
                    const uint32_t vbase = smV_u + (uint32_t)(kc * 32) * 4;
#pragma unroll
                    for (int ks = 0; ks < 4; ks++) {
                        unsigned af[2][4], bfr[4][2];
#pragma unroll
                        for (int mtw = 0; mtw < 2; mtw++)
                            LDSM_X4(af[mtw][0], af[mtw][1], af[mtw][2], af[mtw][3],
                                    abase + (aoff[mtw] + ks * 8) * 4);
#pragma unroll
                        for (int p = 0; p < 2; p++)
                            LDSM_X4(bfr[2 * p][0], bfr[2 * p][1], bfr[2 * p + 1][0], bfr[2 * p + 1][1],
                                    vbase + (voff[p] + ks * 8) * 4);
#pragma unroll
                        for (int mtw = 0; mtw < 2; mtw++)
#pragma unroll
                            for (int ntw = 0; ntw < 4; ntw++)
                                mma_bf16(acc[mtw][ntw], af[mtw], bfr[ntw]);
                    }
                }
            } else {
                const uint32_t ebase = smE_u + (uint32_t)cur * (STG_A * 4);
                const uint32_t ubase = smU_u + (uint32_t)cur * (STG_U * 4);
#pragma unroll
                for (int ks = 0; ks < 4; ks++) {
                    unsigned af[2][4], bfr[4][2];
#pragma unroll
                    for (int mtw = 0; mtw < 2; mtw++)
                        LDSM_X4(af[mtw][0], af[mtw][1], af[mtw][2], af[mtw][3],
                                ebase + (eoff[mtw] + ks * 8) * 4);
#pragma unroll
                    for (int p = 0; p < 2; p++)
                        LDSM_X4(bfr[2 * p][0], bfr[2 * p][1], bfr[2 * p + 1][0], bfr[2 * p + 1][1],
                                ubase + (uoff[p] + ks * 8) * 4);
#pragma unroll
                    for (int mtw = 0; mtw < 2; mtw++)
#pragma unroll
                        for (int ntw = 0; ntw < 4; ntw++)
                            mma_bf16(acc[mtw][ntw], af[mtw], bfr[ntw]);
                }
            }

            if (kc + 1 < 16) {
                const int nb = (kc + 1) & 1;
                if (isR) {
                    if (doR) {
                        unsigned* Hd = smH + nb * STG_A;
                        *(uint4*)&Hd[ldrow * ASTR + kcol]             = n0r;
                        *(uint4*)&Hd[ldrow * ASTR + kcol + 16]        = n1r;
                        *(uint4*)&Hd[(ldrow + 64) * ASTR + kcol]      = n2r;
                        *(uint4*)&Hd[(ldrow + 64) * ASTR + kcol + 16] = n3r;
                    }
                } else {
                    unsigned* Ed = smE + nb * STG_A;
                    unsigned* Ud = smU + nb * STG_U;
                    *(uint4*)&Ed[edst[0]] = n0r;
                    *(uint4*)&Ed[edst[1]] = n1r;
                    *(uint4*)&Ed[edst[2]] = n2r;
                    *(uint4*)&Ed[edst[3]] = n3r;
                    *(uint4*)&Ud[udst[0]] = nu0;
                    *(uint4*)&Ud[udst[1]] = nu1;
                }
            }
            __syncthreads();
        }

        // recurrent accum -> G tile (overlays h staging); input accum -> z ring (global)
        if (isR) {
            if (doR) {
#pragma unroll
                for (int mtw = 0; mtw < 2; mtw++)
#pragma unroll
                    for (int ntw = 0; ntw < 4; ntw++) {
                        int lr = wm + mtw * 16 + (lane >> 2);
                        int lc = wn + ntw * 8 + (lane & 3) * 2;
                        smG[lr * GS + lc]           = acc[mtw][ntw][0];
                        smG[lr * GS + lc + 1]       = acc[mtw][ntw][1];
                        smG[(lr + 8) * GS + lc]     = acc[mtw][ntw][2];
                        smG[(lr + 8) * GS + lc + 1] = acc[mtw][ntw][3];
                    }
            }
        } else if (t + 1 < SEQL) {
            float* zw = g_zring[(t + 1) & 1];
#pragma unroll
            for (int mtw = 0; mtw < 2; mtw++)
#pragma unroll
                for (int ntw = 0; ntw < 4; ntw++) {
                    int r = m0 + wm + mtw * 16 + (lane >> 2);
                    int c = n0 + wn + ntw * 8 + (lane & 3) * 2;
                    float2 v0; v0.x = acc[mtw][ntw][0]; v0.y = acc[mtw][ntw][1];
                    float2 v1; v1.x = acc[mtw][ntw][2]; v1.y = acc[mtw][ntw][3];
                    *(float2*)&zw[(size_t)r * NG + c] = v0;
                    *(float2*)&zw[(size_t)(r + 8) * NG + c] = v1;
                }
        }
        __syncthreads();

        if (doR) {
            // fused LSTM cell (all 512 threads, 2 items each)
            unsigned* hbout = g_hb[(t & 1) ^ 1];
#pragma unroll
            for (int it = 0; it < 2; it++) {
                int lr = zlr0 + it * 64;
                int m = m0 + lr;
                float4 z0 = zpre[it][0];
                float4 z1 = zpre[it][1];
                const float* Gp = &smG[lr * GS + zjp * 8];

                float i0 = fsig(Gp[0] + z0.x + bb[0]);
                float f0 = fsig(Gp[1] + z0.y + bb[1]);
                float g0 = tanhf(Gp[2] + z0.z + bb[2]);
                float o0 = fsig(Gp[3] + z0.w + bb[3]);
                float i1 = fsig(Gp[4] + z1.x + bb[4]);
                float f1 = fsig(Gp[5] + z1.y + bb[5]);
                float g1 = tanhf(Gp[6] + z1.z + bb[6]);
                float o1 = fsig(Gp[7] + z1.w + bb[7]);

                float cn0 = f0 * creg[it][0] + i0 * g0;
                float cn1 = f1 * creg[it][1] + i1 * g1;
                creg[it][0] = cn0; creg[it][1] = cn1;

                float h0v = o0 * tanhf(cn0);
                float h1v = o1 * tanhf(cn1);
                hbout[m * 512 + nsl * 8 + zjp] = pack_bf2(h0v, h1v);
                if (t == SEQL - 1) {
                    float2 hf; hf.x = h0v; hf.y = h1v;
                    *(float2*)&g_h[0][m * HIDN + nsl * 16 + zjp * 2] = hf;
                }
            }
            __syncthreads();   // G reads done before next step's h staging overwrites it

            if (t < SEQL - 1) {
                if (tid == 0) {
                    __threadfence();
                    atomicAdd(bar, 1u);
                    const unsigned target = 64u * (t + 1);
                    unsigned v;
                    do {
                        asm volatile("ld.acquire.gpu.u32 %0, [%1];"
                                     : "=r"(v) : "l"(bar) : "memory");
                    } while (v < target);
                }
                __syncthreads();
            }
        }
    }
}

// ---------------- tf32 output projection: out = h_final @ W^T + b ----------------
__global__ __launch_bounds__(128)
void out_gemm_kernel(const float* __restrict__ W,
                     const float* __restrict__ biasp,
                     float* __restrict__ Cout)
{
    const int tid  = threadIdx.x;
    const int lane = tid & 31;
    const int warp = tid >> 5;
    const int wm = (warp >> 1) * 64;
    const int wn = (warp & 1) * 32;
    const int n0 = blockIdx.x * BN;
    const int m0 = blockIdx.y * BM;

    __shared__ struct { float A[2][BM * AS]; float B[2][BN * BSS]; } sm;

    const float* Ain = g_h[0];
    const int kcol  = (tid & 3) * 4;
    const int ldrow = tid >> 2;

    const float* arp[4];
#pragma unroll
    for (int i = 0; i < 4; i++)
        arp[i] = Ain + (size_t)(m0 + ldrow + 32 * i) * HIDN + kcol;
    const float* brp[2];
#pragma unroll
    for (int i = 0; i < 2; i++)
        brp[i] = W + (size_t)(n0 + ldrow + 32 * i) * HIDN + kcol;

    float4 areg[4], breg[2];
    float acc[4][4][4];
#pragma unroll
    for (int a = 0; a < 4; a++)
#pragma unroll
        for (int b_ = 0; b_ < 4; b_++)
#pragma unroll
            for (int c_ = 0; c_ < 4; c_++) acc[a][b_][c_] = 0.f;

#pragma unroll
    for (int i = 0; i < 4; i++) areg[i] = *(const float4*)(arp[i]);
#pragma unroll
    for (int i = 0; i < 2; i++) breg[i] = *(const float4*)(brp[i]);
#pragma unroll
    for (int i = 0; i < 4; i++) {
        float4 v = areg[i];
        v.x = f2tf32(v.x); v.y = f2tf32(v.y); v.z = f2tf32(v.z); v.w = f2tf32(v.w);
        *(float4*)&sm.A[0][(ldrow + 32 * i) * AS + kcol] = v;
    }
#pragma unroll
    for (int i = 0; i < 2; i++) {
        float4 v = breg[i];
        v.x = f2tf32(v.x); v.y = f2tf32(v.y); v.z = f2tf32(v.z); v.w = f2tf32(v.w);
        *(float4*)&sm.B[0][(ldrow + 32 * i) * BSS + kcol] = v;
    }
    __syncthreads();

    const int NCH = HIDN / BK;
    for (int kc = 0; kc < NCH; kc++) {
        int cur = kc & 1;
        if (kc + 1 < NCH) {
#pragma unroll
            for (int i = 0; i < 4; i++) areg[i] = *(const float4*)(arp[i] + (kc + 1) * BK);
#pragma unroll
            for (int i = 0; i < 2; i++) breg[i] = *(const float4*)(brp[i] + (kc + 1) * BK);
        }
#pragma unroll
        for (int k8 = 0; k8 < BK; k8 += 8) {
            uint32_t af[4][4], bfr[4][2];
#pragma unroll
            for (int mt = 0; mt < 4; mt++) {
                const float* ap = &sm.A[cur][(wm + mt * 16 + (lane >> 2)) * AS + k8 + (lane & 3)];
                af[mt][0] = __float_as_uint(ap[0]);
                af[mt][1] = __float_as_uint(ap[8 * AS]);
                af[mt][2] = __float_as_uint(ap[4]);
                af[mt][3] = __float_as_uint(ap[8 * AS + 4]);
            }
#pragma unroll
            for (int nt = 0; nt < 4; nt++) {
                const float* bp = &sm.B[cur][(wn + nt * 8 + (lane >> 2)) * BSS + k8 + (lane & 3)];
                bfr[nt][0] = __float_as_uint(bp[0]);
                bfr[nt][1] = __float_as_uint(bp[4]);
            }
#pragma unroll
            for (int mt = 0; mt < 4; mt++)
#pragma unroll
                for (int nt = 0; nt < 4; nt++)
                    asm volatile(
                        "mma.sync.aligned.m16n8k8.row.col.f32.tf32.tf32.f32 "
                        "{%0,%1,%2,%3}, {%4,%5,%6,%7}, {%8,%9}, {%0,%1,%2,%3};"
                        : "+f"(acc[mt][nt][0]), "+f"(acc[mt][nt][1]),
                          "+f"(acc[mt][nt][2]), "+f"(acc[mt][nt][3])
                        : "r"(af[mt][0]), "r"(af[mt][1]), "r"(af[mt][2]), "r"(af[mt][3]),
                          "r"(bfr[nt][0]), "r"(bfr[nt][1]));
        }
        if (kc + 1 < NCH) {
            int nxt = cur ^ 1;
#pragma unroll
            for (int i = 0; i < 4; i++) {
                float4 v = areg[i];
                v.x = f2tf32(v.x); v.y = f2tf32(v.y); v.z = f2tf32(v.z); v.w = f2tf32(v.w);
                *(float4*)&sm.A[nxt][(ldrow + 32 * i) * AS + kcol] = v;
            }
#pragma unroll
            for (int i = 0; i < 2; i++) {
                float4 v = breg[i];
                v.x = f2tf32(v.x); v.y = f2tf32(v.y); v.z = f2tf32(v.z); v.w = f2tf32(v.w);
                *(float4*)&sm.B[nxt][(ldrow + 32 * i) * BSS + kcol] = v;
            }
        }
        __syncthreads();
    }

#pragma unroll
    for (int mt = 0; mt < 4; mt++) {
#pragma unroll
        for (int nt = 0; nt < 4; nt++) {
            int r = m0 + wm + mt * 16 + (lane >> 2);
            int cidx = n0 + wn + nt * 8 + (lane & 3) * 2;
            float2 bv = *(const float2*)&biasp[cidx];
            float2 v0; v0.x = acc[mt][nt][0] + bv.x; v0.y = acc[mt][nt][1] + bv.y;
            float2 v1; v1.x = acc[mt][nt][2] + bv.x; v1.y = acc[mt][nt][3] + bv.y;
            *(float2*)&Cout[(size_t)r * NCLS + cidx] = v0;
            *(float2*)&Cout[(size_t)(r + 8) * NCLS + cidx] = v1;
        }
    }
}

// ---------------- launch ----------------
extern "C" void kernel_launch(void* const* d_in, const int* in_sizes, int n_in,
                              void* d_out, int out_size)
{
    const int*   X   = (const int*)  d_in[0];
    const float* h0  = (const float*)d_in[1];
    const float* c0  = (const float*)d_in[2];
    const float* emb = (const float*)d_in[3];
    const float* Ui  = (const float*)d_in[4];
    const float* Vi  = (const float*)d_in[5];
    const float* bi  = (const float*)d_in[6];
    const float* Uf  = (const float*)d_in[7];
    const float* Vf  = (const float*)d_in[8];
    const float* bf  = (const float*)d_in[9];
    const float* Uc  = (const float*)d_in[10];
    const float* Vc  = (const float*)d_in[11];
    const float* bc  = (const float*)d_in[12];
    const float* Uo  = (const float*)d_in[13];
    const float* Vo  = (const float*)d_in[14];
    const float* bo  = (const float*)d_in[15];
    const float* W   = (const float*)d_in[16];
    const float* b   = (const float*)d_in[17];
    float* out = (float*)d_out;

    cudaFuncSetAttribute(lstm_fused_kernel,
                         cudaFuncAttributeMaxDynamicSharedMemorySize, SMEM_P_BYTES);

    // 1) pack weights (bf16 interleaved), biases, init state, reset barriers
    pack_kernel<<<(NG * (HIDN / 2) + 255) / 256, 256>>>(Ui, Vi, bi, Uf, Vf, bf,
                                                        Uc, Vc, bc, Uo, Vo, bo, h0, c0);
    pack_emb_kernel<<<(int)(((size_t)NCLS * (EMBD / 2) + 255) / 256), 256>>>(emb);

    // 2) warp-specialized fused kernel: input GEMM rides inside the persistent steps
    lstm_fused_kernel<<<NCTA, PTHREADS, SMEM_P_BYTES>>>(X);

    // 3) output projection (tf32): out = h_final @ W^T + b
    out_gemm_kernel<<<dim3(NCLS / BN, BATCH / BM), 128>>>(W, b, out);
}

// round 13
// speedup vs baseline: 1.3713x; 1.3713x over previous
#include <cuda_runtime.h>
#include <cuda_bf16.h>
#include <cstdint>
#include <cmath>

#define HIDN 1024
#define EMBD 1024
#define BATCH 256
#define SEQL 128
#define NCLS 32000
#define NG   4096   /* 4*HIDN, gate-interleaved: n = 4*j + g */

#define BM 128
#define BN 64
#define BK 16
#define AS 20
#define BSS 20
#define GS 68
#define VSTR 516
#define ASTR 36          /* input-GEMM stage stride (u32) */
#define STG_A (128 * ASTR)
#define ASTR2 68         /* steps stage stride for 64-half2 chunks (4*row mod 32 distinct) */
#define STG_A2 (128 * ASTR2)

#define NCTA 128
#define PTHREADS 256

// input-GEMM cp.async pipeline geometry
#define IG_STAGE_U32 (2 * 128 * ASTR)   /* A(128x36) + B(128x36) u32 per stage = 9216 */
#define IG_STAGE_B   (IG_STAGE_U32 * 4) /* 36864 B */
#define IG_BOFF_B    (128 * ASTR * 4)   /* B region offset within stage = 18432 B */
#define IG_SMEM_B    (3 * IG_STAGE_B)   /* 110592 B */

// steps kernel smem: V resident + 2 x (128 x 68) staging; G tile overlays staging
#define SMEM_P_BYTES ((64 * VSTR + 2 * STG_A2) * 4)   /* 132096 + 69632 = 201728 */

// ---------------- device scratch (no allocations allowed) ----------------
static __device__ unsigned g_Ub[NG * (HIDN / 2)];            // 8 MB interleaved U, bf16x2
static __device__ unsigned g_Vb[NG * (HIDN / 2)];            // 8 MB interleaved V, bf16x2
static __device__ unsigned g_Eb[(size_t)NCLS * (EMBD / 2)];  // 64 MB emb, bf16x2
static __device__ float    g_ball[NG];
static __device__ float    g_Zin[(size_t)SEQL * BATCH * NG]; // 512 MB input-side gates
static __device__ float    g_h[2][BATCH * HIDN];             // fp32 h (final proj reads [0])
static __device__ unsigned g_hb[2][BATCH * (HIDN / 2)];      // bf16x2 h ping-pong
static __device__ float    g_c[BATCH * HIDN];
static __device__ unsigned g_barA[32];                       // 2 barrier counters (slots 0,16)

// ---------------- helpers ----------------
__device__ __forceinline__ float f2tf32(float x) {
    uint32_t r;
    asm("cvt.rna.tf32.f32 %0, %1;" : "=r"(r) : "f"(x));
    return __uint_as_float(r);
}
__device__ __forceinline__ unsigned pack_bf2(float a, float b) {
    __nv_bfloat162 v = __floats2bfloat162_rn(a, b);
    return *reinterpret_cast<unsigned*>(&v);
}
__device__ __forceinline__ float fsig(float x) {
    return __fdividef(1.f, 1.f + __expf(-x));
}
__device__ __forceinline__ void mma_bf16(float* acc, const unsigned* a, const unsigned* b) {
    asm volatile(
        "mma.sync.aligned.m16n8k16.row.col.f32.bf16.bf16.f32 "
        "{%0,%1,%2,%3}, {%4,%5,%6,%7}, {%8,%9}, {%0,%1,%2,%3};"
        : "+f"(acc[0]), "+f"(acc[1]), "+f"(acc[2]), "+f"(acc[3])
        : "r"(a[0]), "r"(a[1]), "r"(a[2]), "r"(a[3]), "r"(b[0]), "r"(b[1]));
}
__device__ __forceinline__ uint32_t smem_u32(const void* p) {
    uint32_t a;
    asm("{ .reg .u64 t; cvta.to.shared.u64 t, %1; cvt.u32.u64 %0, t; }" : "=r"(a) : "l"(p));
    return a;
}
#define LDSM_X4(r0, r1, r2, r3, addr) \
    asm volatile("ldmatrix.sync.aligned.m8n8.x4.shared.b16 {%0,%1,%2,%3}, [%4];" \
                 : "=r"(r0), "=r"(r1), "=r"(r2), "=r"(r3) : "r"(addr))
#define CP_ASYNC16(dst, src) \
    asm volatile("cp.async.cg.shared.global [%0], [%1], 16;" :: "r"(dst), "l"(src))
#define CP_COMMIT() asm volatile("cp.async.commit_group;" ::: "memory")
#define CP_WAIT1()  asm volatile("cp.async.wait_group 1;" ::: "memory")

// ---------------- pack: interleave U/V (bf16), biases, init state ----------------
__global__ void pack_kernel(const float* __restrict__ Ui, const float* __restrict__ Vi, const float* __restrict__ bi,
                            const float* __restrict__ Uf, const float* __restrict__ Vf, const float* __restrict__ bf,
                            const float* __restrict__ Uc, const float* __restrict__ Vc, const float* __restrict__ bc,
                            const float* __restrict__ Uo, const float* __restrict__ Vo, const float* __restrict__ bo,
                            const float* __restrict__ h0, const float* __restrict__ c0)
{
    int idx = blockIdx.x * blockDim.x + threadIdx.x;
    if (idx >= NG * (HIDN / 2)) return;
    if (idx < 32) g_barA[idx] = 0u;
    int n = idx >> 9;
    int k2 = idx & 511;
    int j = n >> 2, g = n & 3;
    const float *U, *V, *bb;
    if (g == 0)      { U = Ui; V = Vi; bb = bi; }
    else if (g == 1) { U = Uf; V = Vf; bb = bf; }
    else if (g == 2) { U = Uc; V = Vc; bb = bc; }
    else             { U = Uo; V = Vo; bb = bo; }
    const float* Up = U + (size_t)j * HIDN + 2 * k2;
    const float* Vp = V + (size_t)j * HIDN + 2 * k2;
    g_Ub[idx] = pack_bf2(Up[0], Up[1]);
    g_Vb[idx] = pack_bf2(Vp[0], Vp[1]);
    if (k2 == 0) g_ball[n] = bb[j];
    if (idx < BATCH * (HIDN / 2)) {
        g_hb[0][idx] = pack_bf2(h0[2 * idx], h0[2 * idx + 1]);
        float2 hv; hv.x = h0[2 * idx]; hv.y = h0[2 * idx + 1];
        *(float2*)&g_h[0][2 * idx] = hv;
        float2 cv; cv.x = c0[2 * idx]; cv.y = c0[2 * idx + 1];
        *(float2*)&g_c[2 * idx] = cv;
    }
}

__global__ void pack_emb_kernel(const float* __restrict__ emb)
{
    size_t idx = (size_t)blockIdx.x * blockDim.x + threadIdx.x;
    if (idx >= (size_t)NCLS * (EMBD / 2)) return;
    g_Eb[idx] = pack_bf2(emb[2 * idx], emb[2 * idx + 1]);
}

// ---------------- bf16 input GEMM: Zin = gather(emb,X) @ Uall^T + ball ----------------
// grid (32, 256), 256 threads, CTA tile 128x128, warp tile 64x32.
// cp.async 3-stage pipeline, K-chunk 32 half2 (16 chunks), ldmatrix frags. (R10-identical)
__global__ __launch_bounds__(256, 2)
void input_gemm_kernel(const int* __restrict__ Xids)
{
    extern __shared__ unsigned igsm[];
    __shared__ int vrow[128];

    const int tid  = threadIdx.x;
    const int lane = tid & 31;
    const int warp = tid >> 5;
    const int wm = (warp >> 2) * 64;
    const int wn = (warp & 3) * 32;
    const int n0 = blockIdx.x * 128;
    const int m0 = blockIdx.y * 128;

    if (tid < 128) {
        int r = m0 + tid;
        vrow[tid] = Xids[(r & 255) * SEQL + (r >> 8)];
    }
    __syncthreads();

    const uint32_t sbase = smem_u32(igsm);

    const unsigned* srcA[4];
    const unsigned* srcB[4];
    uint32_t dstoff[4];
#pragma unroll
    for (int i = 0; i < 4; i++) {
        int idx = tid + i * 256;
        int row = idx >> 3, cb = idx & 7;
        srcA[i] = g_Eb + (size_t)vrow[row] * 512 + cb * 4;
        srcB[i] = g_Ub + (size_t)(n0 + row) * 512 + cb * 4;
        dstoff[i] = (uint32_t)(row * ASTR + cb * 4) * 4;
    }

    uint32_t aoff[4];
#pragma unroll
    for (int mt = 0; mt < 4; mt++)
        aoff[mt] = (uint32_t)(wm + mt * 16 + (lane & 7) + ((lane >> 3) & 1) * 8) * ASTR
                 + ((lane >> 4) & 1) * 4;
    uint32_t boff[2];
#pragma unroll
    for (int p = 0; p < 2; p++)
        boff[p] = (uint32_t)(wn + p * 16 + (lane & 7) + ((lane >> 4) & 1) * 8) * ASTR
                + ((lane >> 3) & 1) * 4;

    float acc[4][4][4];
#pragma unroll
    for (int a = 0; a < 4; a++)
#pragma unroll
        for (int b_ = 0; b_ < 4; b_++)
#pragma unroll
            for (int c_ = 0; c_ < 4; c_++) acc[a][b_][c_] = 0.f;

    auto issue = [&](int chunk, int stage) {
        uint32_t base = sbase + (uint32_t)stage * IG_STAGE_B;
#pragma unroll
        for (int i = 0; i < 4; i++) {
            CP_ASYNC16(base + dstoff[i], srcA[i] + chunk * 32);
            CP_ASYNC16(base + IG_BOFF_B + dstoff[i], srcB[i] + chunk * 32);
        }
        CP_COMMIT();
    };

    issue(0, 0);
    issue(1, 1);

    int cur = 0, nxt = 2;
    for (int kc = 0; kc < 16; kc++) {
        CP_WAIT1();
        __syncthreads();

        const uint32_t abase = sbase + (uint32_t)cur * IG_STAGE_B;
        const uint32_t bbase = abase + IG_BOFF_B;
#pragma unroll
        for (int ks = 0; ks < 4; ks++) {
            unsigned af[4][4], bfr[4][2];
#pragma unroll
            for (int mt = 0; mt < 4; mt++)
                LDSM_X4(af[mt][0], af[mt][1], af[mt][2], af[mt][3],
                        abase + (aoff[mt] + ks * 8) * 4);
#pragma unroll
            for (int p = 0; p < 2; p++)
                LDSM_X4(bfr[2 * p][0], bfr[2 * p][1], bfr[2 * p + 1][0], bfr[2 * p + 1][1],
                        bbase + (boff[p] + ks * 8) * 4);
#pragma unroll
            for (int mt = 0; mt < 4; mt++)
#pragma unroll
                for (int nt = 0; nt < 4; nt++)
                    mma_bf16(acc[mt][nt], af[mt], bfr[nt]);
        }
        if (kc + 2 < 16) issue(kc + 2, nxt);
        else CP_COMMIT();
        cur = (cur == 2) ? 0 : cur + 1;
        nxt = (nxt == 2) ? 0 : nxt + 1;
    }

#pragma unroll
    for (int mt = 0; mt < 4; mt++) {
#pragma unroll
        for (int nt = 0; nt < 4; nt++) {
            int r = m0 + wm + mt * 16 + (lane >> 2);
            int cidx = n0 + wn + nt * 8 + (lane & 3) * 2;
            float2 bv = *(const float2*)&g_ball[cidx];
            float2 o0; o0.x = acc[mt][nt][0] + bv.x; o0.y = acc[mt][nt][1] + bv.y;
            float2 o1; o1.x = acc[mt][nt][2] + bv.x; o1.y = acc[mt][nt][3] + bv.y;
            *(float2*)&g_Zin[(size_t)r * NG + cidx] = o0;
            *(float2*)&g_Zin[(size_t)(r + 8) * NG + cidx] = o1;
        }
    }
}

// ---------------- persistent recurrent kernel (R10 + K-chunk 64, 8 syncs/step) ----------------
__global__ __launch_bounds__(PTHREADS, 1)
void lstm_persistent_kernel()
{
    extern __shared__ unsigned smem[];
    unsigned* smV = smem;
    unsigned* smA = smem + 64 * VSTR;
    float*    smG = (float*)(smem + 64 * VSTR);

    const int tid  = threadIdx.x;
    const int lane = tid & 31;
    const int warp = tid >> 5;
    const int wm = (warp >> 1) * 32;
    const int wn = (warp & 1) * 32;
    const int bid = blockIdx.x;
    const int m0  = (bid & 1) * 128;
    const int nsl = bid >> 1;
    const int n0  = nsl * 64;
    unsigned* bar = &g_barA[(bid & 1) * 16];

    for (int i = tid; i < 64 * 128; i += PTHREADS) {
        int n = i >> 7, k4 = (i & 127) * 4;
        *(uint4*)&smV[n * VSTR + k4] = *(const uint4*)&g_Vb[(size_t)(n0 + n) * 512 + k4];
    }

    float creg[4][2];
#pragma unroll
    for (int it = 0; it < 4; it++) {
        int idx = tid + it * PTHREADS;
        int lr = idx >> 3, jp = idx & 7;
        float2 cv = *(const float2*)&g_c[(m0 + lr) * HIDN + nsl * 16 + jp * 2];
        creg[it][0] = cv.x; creg[it][1] = cv.y;
    }

    const uint32_t smA_u = smem_u32(smA);
    const uint32_t smV_u = smem_u32(smV);

    uint32_t aoff[2];
#pragma unroll
    for (int mt = 0; mt < 2; mt++)
        aoff[mt] = (uint32_t)(wm + mt * 16 + (lane & 7) + ((lane >> 3) & 1) * 8) * ASTR2
                 + ((lane >> 4) & 1) * 4;
    uint32_t voff[2];
#pragma unroll
    for (int p = 0; p < 2; p++)
        voff[p] = (uint32_t)(wn + p * 16 + (lane & 7) + ((lane >> 4) & 1) * 8) * VSTR
                + ((lane >> 3) & 1) * 4;

    const int kcol  = (tid & 3) * 4;   // u32 offset within first 16 of a 64-unit row
    const int ldrow = tid >> 2;        // 0..63

    // Zin/epilogue mapping
    const int zlr0 = tid >> 3, zjp = tid & 7;

    // prefetch Zin for step 0
    float4 zpre[4][2];
#pragma unroll
    for (int it = 0; it < 4; it++) {
        size_t zb = ((size_t)(m0 + zlr0 + it * 32)) * NG + n0 + zjp * 8;
        zpre[it][0] = *(const float4*)&g_Zin[zb];
        zpre[it][1] = *(const float4*)&g_Zin[zb + 4];
    }
    __syncthreads();

    for (int t = 0; t < SEQL; t++) {
        const unsigned* hin = g_hb[t & 1];
        const unsigned* arp0 = hin + (size_t)(m0 + ldrow) * 512 + kcol;
        const unsigned* arp1 = hin + (size_t)(m0 + ldrow + 64) * 512 + kcol;

        float acc[2][4][4];
#pragma unroll
        for (int a = 0; a < 2; a++)
#pragma unroll
            for (int b_ = 0; b_ < 4; b_++)
#pragma unroll
                for (int c_ = 0; c_ < 4; c_++) acc[a][b_][c_] = 0.f;

        // K-chunk = 64 half2 (128 bf16), 8 iterations; per-thread 8 uint4 per chunk
        // thread covers row ldrow and ldrow+64, u32 offsets kcol + 16q (q=0..3)
        uint4 pre[8];
#pragma unroll
        for (int q = 0; q < 4; q++) {
            pre[q]     = *(const uint4*)(arp0 + 16 * q);
            pre[4 + q] = *(const uint4*)(arp1 + 16 * q);
        }
#pragma unroll
        for (int q = 0; q < 4; q++) {
            *(uint4*)&smA[ldrow * ASTR2 + kcol + 16 * q]        = pre[q];
            *(uint4*)&smA[(ldrow + 64) * ASTR2 + kcol + 16 * q] = pre[4 + q];
        }
        __syncthreads();

        for (int kc = 0; kc < 8; kc++) {
            const int cur = kc & 1;
            if (kc + 1 < 8) {
#pragma unroll
                for (int q = 0; q < 4; q++) {
                    pre[q]     = *(const uint4*)(arp0 + (kc + 1) * 64 + 16 * q);
                    pre[4 + q] = *(const uint4*)(arp1 + (kc + 1) * 64 + 16 * q);
                }
            }
            const uint32_t abase = smA_u + (uint32_t)cur * (STG_A2 * 4);
            const uint32_t vbase = smV_u + (uint32_t)(kc * 64) * 4;
#pragma unroll
            for (int ks = 0; ks < 8; ks++) {
                unsigned af[2][4], bfr[4][2];
#pragma unroll
                for (int mtw = 0; mtw < 2; mtw++)
                    LDSM_X4(af[mtw][0], af[mtw][1], af[mtw][2], af[mtw][3],
                            abase + (aoff[mtw] + ks * 8) * 4);
#pragma unroll
                for (int p = 0; p < 2; p++)
                    LDSM_X4(bfr[2 * p][0], bfr[2 * p][1], bfr[2 * p + 1][0], bfr[2 * p + 1][1],
                            vbase + (voff[p] + ks * 8) * 4);
#pragma unroll
                for (int mtw = 0; mtw < 2; mtw++)
#pragma unroll
                    for (int ntw = 0; ntw < 4; ntw++)
                        mma_bf16(acc[mtw][ntw], af[mtw], bfr[ntw]);
            }
            if (kc + 1 < 8) {
                unsigned* Ad = smA + ((kc + 1) & 1) * STG_A2;
#pragma unroll
                for (int q = 0; q < 4; q++) {
                    *(uint4*)&Ad[ldrow * ASTR2 + kcol + 16 * q]        = pre[q];
                    *(uint4*)&Ad[(ldrow + 64) * ASTR2 + kcol + 16 * q] = pre[4 + q];
                }
            }
            __syncthreads();
        }

        // accum -> smem gate tile (overlays A staging; all mma reads done)
#pragma unroll
        for (int mtw = 0; mtw < 2; mtw++)
#pragma unroll
            for (int ntw = 0; ntw < 4; ntw++) {
                int lr = wm + mtw * 16 + (lane >> 2);
                int lc = wn + ntw * 8 + (lane & 3) * 2;
                smG[lr * GS + lc]           = acc[mtw][ntw][0];
                smG[lr * GS + lc + 1]       = acc[mtw][ntw][1];
                smG[(lr + 8) * GS + lc]     = acc[mtw][ntw][2];
                smG[(lr + 8) * GS + lc + 1] = acc[mtw][ntw][3];
            }
        __syncthreads();

        // fused LSTM cell (c in registers)
        unsigned* hbout = g_hb[(t & 1) ^ 1];
#pragma unroll
        for (int it = 0; it < 4; it++) {
            int lr = zlr0 + it * 32;
            int m = m0 + lr;
            float4 z0 = zpre[it][0];
            float4 z1 = zpre[it][1];
            const float* Gp = &smG[lr * GS + zjp * 8];

            float i0 = fsig(Gp[0] + z0.x);
            float f0 = fsig(Gp[1] + z0.y);
            float g0 = tanhf(Gp[2] + z0.z);
            float o0 = fsig(Gp[3] + z0.w);
            float i1 = fsig(Gp[4] + z1.x);
            float f1 = fsig(Gp[5] + z1.y);
            float g1 = tanhf(Gp[6] + z1.z);
            float o1 = fsig(Gp[7] + z1.w);

            float cn0 = f0 * creg[it][0] + i0 * g0;
            float cn1 = f1 * creg[it][1] + i1 * g1;
            creg[it][0] = cn0; creg[it][1] = cn1;

            float h0v = o0 * tanhf(cn0);
            float h1v = o1 * tanhf(cn1);
            hbout[m * 512 + nsl * 8 + zjp] = pack_bf2(h0v, h1v);
            if (t == SEQL - 1) {
                float2 hf; hf.x = h0v; hf.y = h1v;
                *(float2*)&g_h[0][m * HIDN + nsl * 16 + zjp * 2] = hf;
            }
        }

        if (t < SEQL - 1) {
            // prefetch next step's Zin BEFORE the barrier (static data; hides DRAM latency)
#pragma unroll
            for (int it = 0; it < 4; it++) {
                size_t zb = ((size_t)(t + 1) * BATCH + m0 + zlr0 + it * 32) * NG + n0 + zjp * 8;
                zpre[it][0] = *(const float4*)&g_Zin[zb];
                zpre[it][1] = *(const float4*)&g_Zin[zb + 4];
            }
            __syncthreads();
            if (tid == 0) {
                __threadfence();
                atomicAdd(bar, 1u);
                const unsigned target = 64u * (t + 1);
                unsigned v;
                do {
                    asm volatile("ld.acquire.gpu.u32 %0, [%1];"
                                 : "=r"(v) : "l"(bar) : "memory");
                } while (v < target);
            }
            __syncthreads();
        }
    }
}

// ---------------- tf32 output projection: out = h_final @ W^T + b ----------------
__global__ __launch_bounds__(128)
void out_gemm_kernel(const float* __restrict__ W,
                     const float* __restrict__ biasp,
                     float* __restrict__ Cout)
{
    const int tid  = threadIdx.x;
    const int lane = tid & 31;
    const int warp = tid >> 5;
    const int wm = (warp >> 1) * 64;
    const int wn = (warp & 1) * 32;
    const int n0 = blockIdx.x * BN;
    const int m0 = blockIdx.y * BM;

    __shared__ struct { float A[2][BM * AS]; float B[2][BN * BSS]; } sm;

    const float* Ain = g_h[0];
    const int kcol  = (tid & 3) * 4;
    const int ldrow = tid >> 2;

    const float* arp[4];
#pragma unroll
    for (int i = 0; i < 4; i++)
        arp[i] = Ain + (size_t)(m0 + ldrow + 32 * i) * HIDN + kcol;
    const float* brp[2];
#pragma unroll
    for (int i = 0; i < 2; i++)
        brp[i] = W + (size_t)(n0 + ldrow + 32 * i) * HIDN + kcol;

    float4 areg[4], breg[2];
    float acc[4][4][4];
#pragma unroll
    for (int a = 0; a < 4; a++)
#pragma unroll
        for (int b_ = 0; b_ < 4; b_++)
#pragma unroll
            for (int c_ = 0; c_ < 4; c_++) acc[a][b_][c_] = 0.f;

#pragma unroll
    for (int i = 0; i < 4; i++) areg[i] = *(const float4*)(arp[i]);
#pragma unroll
    for (int i = 0; i < 2; i++) breg[i] = *(const float4*)(brp[i]);
#pragma unroll
    for (int i = 0; i < 4; i++) {
        float4 v = areg[i];
        v.x = f2tf32(v.x); v.y = f2tf32(v.y); v.z = f2tf32(v.z); v.w = f2tf32(v.w);
        *(float4*)&sm.A[0][(ldrow + 32 * i) * AS + kcol] = v;
    }
#pragma unroll
    for (int i = 0; i < 2; i++) {
        float4 v = breg[i];
        v.x = f2tf32(v.x); v.y = f2tf32(v.y); v.z = f2tf32(v.z); v.w = f2tf32(v.w);
        *(float4*)&sm.B[0][(ldrow + 32 * i) * BSS + kcol] = v;
    }
    __syncthreads();

    const int NCH = HIDN / BK;
    for (int kc = 0; kc < NCH; kc++) {
        int cur = kc & 1;
        if (kc + 1 < NCH) {
#pragma unroll
            for (int i = 0; i < 4; i++) areg[i] = *(const float4*)(arp[i] + (kc + 1) * BK);
#pragma unroll
            for (int i = 0; i < 2; i++) breg[i] = *(const float4*)(brp[i] + (kc + 1) * BK);
        }
#pragma unroll
        for (int k8 = 0; k8 < BK; k8 += 8) {
            uint32_t af[4][4], bfr[4][2];
#pragma unroll
            for (int mt = 0; mt < 4; mt++) {
                const float* ap = &sm.A[cur][(wm + mt * 16 + (lane >> 2)) * AS + k8 + (lane & 3)];
                af[mt][0] = __float_as_uint(ap[0]);
                af[mt][1] = __float_as_uint(ap[8 * AS]);
                af[mt][2] = __float_as_uint(ap[4]);
                af[mt][3] = __float_as_uint(ap[8 * AS + 4]);
            }
#pragma unroll
            for (int nt = 0; nt < 4; nt++) {
                const float* bp = &sm.B[cur][(wn + nt * 8 + (lane >> 2)) * BSS + k8 + (lane & 3)];
                bfr[nt][0] = __float_as_uint(bp[0]);
                bfr[nt][1] = __float_as_uint(bp[4]);
            }
#pragma unroll
            for (int mt = 0; mt < 4; mt++)
#pragma unroll
                for (int nt = 0; nt < 4; nt++)
                    asm volatile(
                        "mma.sync.aligned.m16n8k8.row.col.f32.tf32.tf32.f32 "
                        "{%0,%1,%2,%3}, {%4,%5,%6,%7}, {%8,%9}, {%0,%1,%2,%3};"
                        : "+f"(acc[mt][nt][0]), "+f"(acc[mt][nt][1]),
                          "+f"(acc[mt][nt][2]), "+f"(acc[mt][nt][3])
                        : "r"(af[mt][0]), "r"(af[mt][1]), "r"(af[mt][2]), "r"(af[mt][3]),
                          "r"(bfr[nt][0]), "r"(bfr[nt][1]));
        }
        if (kc + 1 < NCH) {
            int nxt = cur ^ 1;
#pragma unroll
            for (int i = 0; i < 4; i++) {
                float4 v = areg[i];
                v.x = f2tf32(v.x); v.y = f2tf32(v.y); v.z = f2tf32(v.z); v.w = f2tf32(v.w);
                *(float4*)&sm.A[nxt][(ldrow + 32 * i) * AS + kcol] = v;
            }
#pragma unroll
            for (int i = 0; i < 2; i++) {
                float4 v = breg[i];
                v.x = f2tf32(v.x); v.y = f2tf32(v.y); v.z = f2tf32(v.z); v.w = f2tf32(v.w);
                *(float4*)&sm.B[nxt][(ldrow + 32 * i) * BSS + kcol] = v;
            }
        }
        __syncthreads();
    }

#pragma unroll
    for (int mt = 0; mt < 4; mt++) {
#pragma unroll
        for (int nt = 0; nt < 4; nt++) {
            int r = m0 + wm + mt * 16 + (lane >> 2);
            int cidx = n0 + wn + nt * 8 + (lane & 3) * 2;
            float2 bv = *(const float2*)&biasp[cidx];
            float2 v0; v0.x = acc[mt][nt][0] + bv.x; v0.y = acc[mt][nt][1] + bv.y;
            float2 v1; v1.x = acc[mt][nt][2] + bv.x; v1.y = acc[mt][nt][3] + bv.y;
            *(float2*)&Cout[(size_t)r * NCLS + cidx] = v0;
            *(float2*)&Cout[(size_t)(r + 8) * NCLS + cidx] = v1;
        }
    }
}

// ---------------- launch ----------------
extern "C" void kernel_launch(void* const* d_in, const int* in_sizes, int n_in,
                              void* d_out, int out_size)
{
    const int*   X   = (const int*)  d_in[0];
    const float* h0  = (const float*)d_in[1];
    const float* c0  = (const float*)d_in[2];
    const float* emb = (const float*)d_in[3];
    const float* Ui  = (const float*)d_in[4];
    const float* Vi  = (const float*)d_in[5];
    const float* bi  = (const float*)d_in[6];
    const float* Uf  = (const float*)d_in[7];
    const float* Vf  = (const float*)d_in[8];
    const float* bf  = (const float*)d_in[9];
    const float* Uc  = (const float*)d_in[10];
    const float* Vc  = (const float*)d_in[11];
    const float* bc  = (const float*)d_in[12];
    const float* Uo  = (const float*)d_in[13];
    const float* Vo  = (const float*)d_in[14];
    const float* bo  = (const float*)d_in[15];
    const float* W   = (const float*)d_in[16];
    const float* b   = (const float*)d_in[17];
    float* out = (float*)d_out;

    cudaFuncSetAttribute(lstm_persistent_kernel,
                         cudaFuncAttributeMaxDynamicSharedMemorySize, SMEM_P_BYTES);
    cudaFuncSetAttribute(input_gemm_kernel,
                         cudaFuncAttributeMaxDynamicSharedMemorySize, IG_SMEM_B);

    // 1) pack weights (bf16 interleaved), biases, init state, reset barriers
    pack_kernel<<<(NG * (HIDN / 2) + 255) / 256, 256>>>(Ui, Vi, bi, Uf, Vf, bf,
                                                        Uc, Vc, bc, Uo, Vo, bo, h0, c0);
    pack_emb_kernel<<<(int)(((size_t)NCLS * (EMBD / 2) + 255) / 256), 256>>>(emb);

    // 2) all input-side gate preactivations (cp.async 3-stage, ldmatrix)
    input_gemm_kernel<<<dim3(NG / 128, (SEQL * BATCH) / 128), 256, IG_SMEM_B>>>(X);

    // 3) all 128 recurrent steps in ONE persistent kernel (V resident, K-chunk 64)
    lstm_persistent_kernel<<<NCTA, PTHREADS, SMEM_P_BYTES>>>();

    // 4) output projection (tf32): out = h_final @ W^T + b
    out_gemm_kernel<<<dim3(NCLS / BN, BATCH / BM), 128>>>(W, b, out);
}

// round 14
// speedup vs baseline: 1.3891x; 1.0129x over previous
#include <cuda_runtime.h>
#include <cuda_bf16.h>
#include <cstdint>
#include <cmath>

#define HIDN 1024
#define EMBD 1024
#define BATCH 256
#define SEQL 128
#define NCLS 32000
#define NG   4096   /* 4*HIDN, gate-interleaved: n = 4*j + g */

#define BM 128
#define BN 64
#define BK 16
#define AS 20
#define BSS 20
#define GS 68
#define VSTR 516
#define ASTR 36          /* stage stride (u32), conflict-free for ldmatrix */
#define STG_A (128 * ASTR)

#define NCTA 128
#define PTHREADS 512     /* 16 warps: two DECOUPLED 8-warp K-groups */

// input-GEMM cp.async pipeline geometry
#define IG_STAGE_U32 (2 * 128 * ASTR)
#define IG_STAGE_B   (IG_STAGE_U32 * 4)
#define IG_BOFF_B    (128 * ASTR * 4)
#define IG_SMEM_B    (3 * IG_STAGE_B)

// steps kernel smem: V resident + 4 stage buffers (2 per K-group); G tiles overlay staging
#define SMEM_P_BYTES ((64 * VSTR) * 4 + 4 * STG_A * 4)   /* 205824 */

// ---------------- device scratch (no allocations allowed) ----------------
static __device__ unsigned g_Ub[NG * (HIDN / 2)];
static __device__ unsigned g_Vb[NG * (HIDN / 2)];
static __device__ unsigned g_Eb[(size_t)NCLS * (EMBD / 2)];
static __device__ float    g_ball[NG];
static __device__ float    g_Zin[(size_t)SEQL * BATCH * NG];
static __device__ float    g_h[2][BATCH * HIDN];
static __device__ unsigned g_hb[2][BATCH * (HIDN / 2)];
static __device__ float    g_c[BATCH * HIDN];
static __device__ unsigned g_barA[32];

// ---------------- helpers ----------------
__device__ __forceinline__ float f2tf32(float x) {
    uint32_t r;
    asm("cvt.rna.tf32.f32 %0, %1;" : "=r"(r) : "f"(x));
    return __uint_as_float(r);
}
__device__ __forceinline__ unsigned pack_bf2(float a, float b) {
    __nv_bfloat162 v = __floats2bfloat162_rn(a, b);
    return *reinterpret_cast<unsigned*>(&v);
}
__device__ __forceinline__ float fsig(float x) {
    return __fdividef(1.f, 1.f + __expf(-x));
}
__device__ __forceinline__ void mma_bf16(float* acc, const unsigned* a, const unsigned* b) {
    asm volatile(
        "mma.sync.aligned.m16n8k16.row.col.f32.bf16.bf16.f32 "
        "{%0,%1,%2,%3}, {%4,%5,%6,%7}, {%8,%9}, {%0,%1,%2,%3};"
        : "+f"(acc[0]), "+f"(acc[1]), "+f"(acc[2]), "+f"(acc[3])
        : "r"(a[0]), "r"(a[1]), "r"(a[2]), "r"(a[3]), "r"(b[0]), "r"(b[1]));
}
__device__ __forceinline__ uint32_t smem_u32(const void* p) {
    uint32_t a;
    asm("{ .reg .u64 t; cvta.to.shared.u64 t, %1; cvt.u32.u64 %0, t; }" : "=r"(a) : "l"(p));
    return a;
}
__device__ __forceinline__ void nbar(int id) {   // named barrier, 256 threads
    asm volatile("bar.sync %0, 256;" :: "r"(id) : "memory");
}
#define LDSM_X4(r0, r1, r2, r3, addr) \
    asm volatile("ldmatrix.sync.aligned.m8n8.x4.shared.b16 {%0,%1,%2,%3}, [%4];" \
                 : "=r"(r0), "=r"(r1), "=r"(r2), "=r"(r3) : "r"(addr))
#define CP_ASYNC16(dst, src) \
    asm volatile("cp.async.cg.shared.global [%0], [%1], 16;" :: "r"(dst), "l"(src))
#define CP_COMMIT() asm volatile("cp.async.commit_group;" ::: "memory")
#define CP_WAIT1()  asm volatile("cp.async.wait_group 1;" ::: "memory")

// ---------------- pack: interleave U/V (bf16), biases, init state ----------------
__global__ void pack_kernel(const float* __restrict__ Ui, const float* __restrict__ Vi, const float* __restrict__ bi,
                            const float* __restrict__ Uf, const float* __restrict__ Vf, const float* __restrict__ bf,
                            const float* __restrict__ Uc, const float* __restrict__ Vc, const float* __restrict__ bc,
                            const float* __restrict__ Uo, const float* __restrict__ Vo, const float* __restrict__ bo,
                            const float* __restrict__ h0, const float* __restrict__ c0)
{
    int idx = blockIdx.x * blockDim.x + threadIdx.x;
    if (idx >= NG * (HIDN / 2)) return;
    if (idx < 32) g_barA[idx] = 0u;
    int n = idx >> 9;
    int k2 = idx & 511;
    int j = n >> 2, g = n & 3;
    const float *U, *V, *bb;
    if (g == 0)      { U = Ui; V = Vi; bb = bi; }
    else if (g == 1) { U = Uf; V = Vf; bb = bf; }
    else if (g == 2) { U = Uc; V = Vc; bb = bc; }
    else             { U = Uo; V = Vo; bb = bo; }
    const float* Up = U + (size_t)j * HIDN + 2 * k2;
    const float* Vp = V + (size_t)j * HIDN + 2 * k2;
    g_Ub[idx] = pack_bf2(Up[0], Up[1]);
    g_Vb[idx] = pack_bf2(Vp[0], Vp[1]);
    if (k2 == 0) g_ball[n] = bb[j];
    if (idx < BATCH * (HIDN / 2)) {
        g_hb[0][idx] = pack_bf2(h0[2 * idx], h0[2 * idx + 1]);
        float2 hv; hv.x = h0[2 * idx]; hv.y = h0[2 * idx + 1];
        *(float2*)&g_h[0][2 * idx] = hv;
        float2 cv; cv.x = c0[2 * idx]; cv.y = c0[2 * idx + 1];
        *(float2*)&g_c[2 * idx] = cv;
    }
}

__global__ void pack_emb_kernel(const float* __restrict__ emb)
{
    size_t idx = (size_t)blockIdx.x * blockDim.x + threadIdx.x;
    if (idx >= (size_t)NCLS * (EMBD / 2)) return;
    g_Eb[idx] = pack_bf2(emb[2 * idx], emb[2 * idx + 1]);
}

// ---------------- bf16 input GEMM (R10-identical) ----------------
__global__ __launch_bounds__(256, 2)
void input_gemm_kernel(const int* __restrict__ Xids)
{
    extern __shared__ unsigned igsm[];
    __shared__ int vrow[128];

    const int tid  = threadIdx.x;
    const int lane = tid & 31;
    const int warp = tid >> 5;
    const int wm = (warp >> 2) * 64;
    const int wn = (warp & 3) * 32;
    const int n0 = blockIdx.x * 128;
    const int m0 = blockIdx.y * 128;

    if (tid < 128) {
        int r = m0 + tid;
        vrow[tid] = Xids[(r & 255) * SEQL + (r >> 8)];
    }
    __syncthreads();

    const uint32_t sbase = smem_u32(igsm);

    const unsigned* srcA[4];
    const unsigned* srcB[4];
    uint32_t dstoff[4];
#pragma unroll
    for (int i = 0; i < 4; i++) {
        int idx = tid + i * 256;
        int row = idx >> 3, cb = idx & 7;
        srcA[i] = g_Eb + (size_t)vrow[row] * 512 + cb * 4;
        srcB[i] = g_Ub + (size_t)(n0 + row) * 512 + cb * 4;
        dstoff[i] = (uint32_t)(row * ASTR + cb * 4) * 4;
    }

    uint32_t aoff[4];
#pragma unroll
    for (int mt = 0; mt < 4; mt++)
        aoff[mt] = (uint32_t)(wm + mt * 16 + (lane & 7) + ((lane >> 3) & 1) * 8) * ASTR
                 + ((lane >> 4) & 1) * 4;
    uint32_t boff[2];
#pragma unroll
    for (int p = 0; p < 2; p++)
        boff[p] = (uint32_t)(wn + p * 16 + (lane & 7) + ((lane >> 4) & 1) * 8) * ASTR
                + ((lane >> 3) & 1) * 4;

    float acc[4][4][4];
#pragma unroll
    for (int a = 0; a < 4; a++)
#pragma unroll
        for (int b_ = 0; b_ < 4; b_++)
#pragma unroll
            for (int c_ = 0; c_ < 4; c_++) acc[a][b_][c_] = 0.f;

    auto issue = [&](int chunk, int stage) {
        uint32_t base = sbase + (uint32_t)stage * IG_STAGE_B;
#pragma unroll
        for (int i = 0; i < 4; i++) {
            CP_ASYNC16(base + dstoff[i], srcA[i] + chunk * 32);
            CP_ASYNC16(base + IG_BOFF_B + dstoff[i], srcB[i] + chunk * 32);
        }
        CP_COMMIT();
    };

    issue(0, 0);
    issue(1, 1);

    int cur = 0, nxt = 2;
    for (int kc = 0; kc < 16; kc++) {
        CP_WAIT1();
        __syncthreads();

        const uint32_t abase = sbase + (uint32_t)cur * IG_STAGE_B;
        const uint32_t bbase = abase + IG_BOFF_B;
#pragma unroll
        for (int ks = 0; ks < 4; ks++) {
            unsigned af[4][4], bfr[4][2];
#pragma unroll
            for (int mt = 0; mt < 4; mt++)
                LDSM_X4(af[mt][0], af[mt][1], af[mt][2], af[mt][3],
                        abase + (aoff[mt] + ks * 8) * 4);
#pragma unroll
            for (int p = 0; p < 2; p++)
                LDSM_X4(bfr[2 * p][0], bfr[2 * p][1], bfr[2 * p + 1][0], bfr[2 * p + 1][1],
                        bbase + (boff[p] + ks * 8) * 4);
#pragma unroll
            for (int mt = 0; mt < 4; mt++)
#pragma unroll
                for (int nt = 0; nt < 4; nt++)
                    mma_bf16(acc[mt][nt], af[mt], bfr[nt]);
        }
        if (kc + 2 < 16) issue(kc + 2, nxt);
        else CP_COMMIT();
        cur = (cur == 2) ? 0 : cur + 1;
        nxt = (nxt == 2) ? 0 : nxt + 1;
    }

#pragma unroll
    for (int mt = 0; mt < 4; mt++) {
#pragma unroll
        for (int nt = 0; nt < 4; nt++) {
            int r = m0 + wm + mt * 16 + (lane >> 2);
            int cidx = n0 + wn + nt * 8 + (lane & 3) * 2;
            float2 bv = *(const float2*)&g_ball[cidx];
            float2 o0; o0.x = acc[mt][nt][0] + bv.x; o0.y = acc[mt][nt][1] + bv.y;
            float2 o1; o1.x = acc[mt][nt][2] + bv.x; o1.y = acc[mt][nt][3] + bv.y;
            *(float2*)&g_Zin[(size_t)r * NG + cidx] = o0;
            *(float2*)&g_Zin[(size_t)(r + 8) * NG + cidx] = o1;
        }
    }
}

// ---------------- persistent recurrent kernel: split-K, DECOUPLED named-barrier groups ----
// Group g (warps 8g..8g+7, 256 thr) accumulates K half g through its OWN pipeline,
// synced by bar.sync(g+1) only. One full __syncthreads separates GEMM from G writes.
__global__ __launch_bounds__(PTHREADS, 1)
void lstm_persistent_kernel()
{
    extern __shared__ unsigned smem[];
    unsigned* smV = smem;                        // 64 x VSTR
    unsigned* smA = smem + 64 * VSTR;            // 4 x STG_A (2 buffers per group)
    float*    smG = (float*)smA;                 // 2 G tiles (overlay staging)

    const int tid   = threadIdx.x;
    const int lane  = tid & 31;
    const int group = tid >> 8;                  // K-half 0/1
    const int gtid  = tid & 255;
    const int gw    = (tid >> 5) & 7;            // warp within group
    const int wm = (gw >> 1) * 32;
    const int wn = (gw & 1) * 32;
    const int bid = blockIdx.x;
    const int m0  = (bid & 1) * 128;
    const int nsl = bid >> 1;
    const int n0  = nsl * 64;
    unsigned* bar = &g_barA[(bid & 1) * 16];

    for (int i = tid; i < 64 * 128; i += PTHREADS) {
        int n = i >> 7, k4 = (i & 127) * 4;
        *(uint4*)&smV[n * VSTR + k4] = *(const uint4*)&g_Vb[(size_t)(n0 + n) * 512 + k4];
    }

    // c slice: 1024 items / 512 threads = 2 per thread
    float creg[2][2];
#pragma unroll
    for (int it = 0; it < 2; it++) {
        int idx = tid + it * PTHREADS;
        int lr = idx >> 3, jp = idx & 7;
        float2 cv = *(const float2*)&g_c[(m0 + lr) * HIDN + nsl * 16 + jp * 2];
        creg[it][0] = cv.x; creg[it][1] = cv.y;
    }

    const uint32_t smA_u = smem_u32(smA);
    const uint32_t smV_u = smem_u32(smV);
    const uint32_t gstage = (uint32_t)group * 2 * STG_A;

    uint32_t aoff[2];
#pragma unroll
    for (int mt = 0; mt < 2; mt++)
        aoff[mt] = (uint32_t)(wm + mt * 16 + (lane & 7) + ((lane >> 3) & 1) * 8) * ASTR
                 + ((lane >> 4) & 1) * 4;
    uint32_t voff[2];
#pragma unroll
    for (int p = 0; p < 2; p++)
        voff[p] = (uint32_t)(wn + p * 16 + (lane & 7) + ((lane >> 4) & 1) * 8) * VSTR
                + ((lane >> 3) & 1) * 4;

    const int kcol  = (gtid & 3) * 4;
    const int ldrow = gtid >> 2;                 // 0..63
    const int kbase = group * 256;               // group's first half2 column
    const int nb    = group + 1;                 // named barrier id

    // Zin / epilogue mapping: 2 items per thread
    const int zlr0 = tid >> 3, zjp = tid & 7;

    float4 zpre[2][2];
#pragma unroll
    for (int it = 0; it < 2; it++) {
        size_t zb = ((size_t)(m0 + zlr0 + it * 64)) * NG + n0 + zjp * 8;
        zpre[it][0] = *(const float4*)&g_Zin[zb];
        zpre[it][1] = *(const float4*)&g_Zin[zb + 4];
    }
    __syncthreads();

    for (int t = 0; t < SEQL; t++) {
        const unsigned* hin = g_hb[t & 1];
        const unsigned* arp0 = hin + (size_t)(m0 + ldrow) * 512 + kbase + kcol;
        const unsigned* arp1 = hin + (size_t)(m0 + ldrow + 64) * 512 + kbase + kcol;

        float acc[2][4][4];
#pragma unroll
        for (int a = 0; a < 2; a++)
#pragma unroll
            for (int b_ = 0; b_ < 4; b_++)
#pragma unroll
                for (int c_ = 0; c_ < 4; c_++) acc[a][b_][c_] = 0.f;

        // stage group-chunk 0
        uint4 a00 = *(const uint4*)arp0;
        uint4 a01 = *(const uint4*)(arp0 + 16);
        uint4 a10 = *(const uint4*)arp1;
        uint4 a11 = *(const uint4*)(arp1 + 16);
        {
            unsigned* Ad = smA + gstage;
            *(uint4*)&Ad[ldrow * ASTR + kcol]             = a00;
            *(uint4*)&Ad[ldrow * ASTR + kcol + 16]        = a01;
            *(uint4*)&Ad[(ldrow + 64) * ASTR + kcol]      = a10;
            *(uint4*)&Ad[(ldrow + 64) * ASTR + kcol + 16] = a11;
        }
        nbar(nb);

        for (int kc = 0; kc < 8; kc++) {
            const int cur = kc & 1;
            if (kc + 1 < 8) {
                a00 = *(const uint4*)(arp0 + (kc + 1) * 32);
                a01 = *(const uint4*)(arp0 + (kc + 1) * 32 + 16);
                a10 = *(const uint4*)(arp1 + (kc + 1) * 32);
                a11 = *(const uint4*)(arp1 + (kc + 1) * 32 + 16);
            }
            const uint32_t abase = smA_u + (gstage + (uint32_t)cur * STG_A) * 4;
            const uint32_t vbase = smV_u + (uint32_t)(kbase + kc * 32) * 4;
#pragma unroll
            for (int ks = 0; ks < 4; ks++) {
                unsigned af[2][4], bfr[4][2];
#pragma unroll
                for (int mtw = 0; mtw < 2; mtw++)
                    LDSM_X4(af[mtw][0], af[mtw][1], af[mtw][2], af[mtw][3],
                            abase + (aoff[mtw] + ks * 8) * 4);
#pragma unroll
                for (int p = 0; p < 2; p++)
                    LDSM_X4(bfr[2 * p][0], bfr[2 * p][1], bfr[2 * p + 1][0], bfr[2 * p + 1][1],
                            vbase + (voff[p] + ks * 8) * 4);
#pragma unroll
                for (int mtw = 0; mtw < 2; mtw++)
#pragma unroll
                    for (int ntw = 0; ntw < 4; ntw++)
                        mma_bf16(acc[mtw][ntw], af[mtw], bfr[ntw]);
            }
            if (kc + 1 < 8) {
                unsigned* Ad = smA + gstage + ((kc + 1) & 1) * STG_A;
                *(uint4*)&Ad[ldrow * ASTR + kcol]             = a00;
                *(uint4*)&Ad[ldrow * ASTR + kcol + 16]        = a01;
                *(uint4*)&Ad[(ldrow + 64) * ASTR + kcol]      = a10;
                *(uint4*)&Ad[(ldrow + 64) * ASTR + kcol + 16] = a11;
            }
            nbar(nb);
        }

        // both groups' GEMMs done before G tiles overwrite any staging
        __syncthreads();

        {
            float* Gg = smG + group * (128 * GS);
#pragma unroll
            for (int mtw = 0; mtw < 2; mtw++)
#pragma unroll
                for (int ntw = 0; ntw < 4; ntw++) {
                    int lr = wm + mtw * 16 + (lane >> 2);
                    int lc = wn + ntw * 8 + (lane & 3) * 2;
                    Gg[lr * GS + lc]           = acc[mtw][ntw][0];
                    Gg[lr * GS + lc + 1]       = acc[mtw][ntw][1];
                    Gg[(lr + 8) * GS + lc]     = acc[mtw][ntw][2];
                    Gg[(lr + 8) * GS + lc + 1] = acc[mtw][ntw][3];
                }
        }
        __syncthreads();

        // fused LSTM cell: gates = G0 + G1 + Zin
        unsigned* hbout = g_hb[(t & 1) ^ 1];
#pragma unroll
        for (int it = 0; it < 2; it++) {
            int lr = zlr0 + it * 64;
            int m = m0 + lr;
            float4 z0 = zpre[it][0];
            float4 z1 = zpre[it][1];
            const float* Gp0 = &smG[lr * GS + zjp * 8];
            const float* Gp1 = Gp0 + 128 * GS;

            float i0 = fsig(Gp0[0] + Gp1[0] + z0.x);
            float f0 = fsig(Gp0[1] + Gp1[1] + z0.y);
            float g0 = tanhf(Gp0[2] + Gp1[2] + z0.z);
            float o0 = fsig(Gp0[3] + Gp1[3] + z0.w);
            float i1 = fsig(Gp0[4] + Gp1[4] + z1.x);
            float f1 = fsig(Gp0[5] + Gp1[5] + z1.y);
            float g1 = tanhf(Gp0[6] + Gp1[6] + z1.z);
            float o1 = fsig(Gp0[7] + Gp1[7] + z1.w);

            float cn0 = f0 * creg[it][0] + i0 * g0;
            float cn1 = f1 * creg[it][1] + i1 * g1;
            creg[it][0] = cn0; creg[it][1] = cn1;

            float h0v = o0 * tanhf(cn0);
            float h1v = o1 * tanhf(cn1);
            hbout[m * 512 + nsl * 8 + zjp] = pack_bf2(h0v, h1v);
            if (t == SEQL - 1) {
                float2 hf; hf.x = h0v; hf.y = h1v;
                *(float2*)&g_h[0][m * HIDN + nsl * 16 + zjp * 2] = hf;
            }
        }

        if (t < SEQL - 1) {
            // prefetch next step's Zin BEFORE the barrier (static data)
#pragma unroll
            for (int it = 0; it < 2; it++) {
                size_t zb = ((size_t)(t + 1) * BATCH + m0 + zlr0 + it * 64) * NG + n0 + zjp * 8;
                zpre[it][0] = *(const float4*)&g_Zin[zb];
                zpre[it][1] = *(const float4*)&g_Zin[zb + 4];
            }
            __syncthreads();
            if (tid == 0) {
                __threadfence();
                atomicAdd(bar, 1u);
                const unsigned target = 64u * (t + 1);
                unsigned v;
                do {
                    asm volatile("ld.acquire.gpu.u32 %0, [%1];"
                                 : "=r"(v) : "l"(bar) : "memory");
                } while (v < target);
            }
            __syncthreads();
        }
    }
}

// ---------------- tf32 output projection: out = h_final @ W^T + b ----------------
__global__ __launch_bounds__(128)
void out_gemm_kernel(const float* __restrict__ W,
                     const float* __restrict__ biasp,
                     float* __restrict__ Cout)
{
    const int tid  = threadIdx.x;
    const int lane = tid & 31;
    const int warp = tid >> 5;
    const int wm = (warp >> 1) * 64;
    const int wn = (warp & 1) * 32;
    const int n0 = blockIdx.x * BN;
    const int m0 = blockIdx.y * BM;

    __shared__ struct { float A[2][BM * AS]; float B[2][BN * BSS]; } sm;

    const float* Ain = g_h[0];
    const int kcol  = (tid & 3) * 4;
    const int ldrow = tid >> 2;

    const float* arp[4];
#pragma unroll
    for (int i = 0; i < 4; i++)
        arp[i] = Ain + (size_t)(m0 + ldrow + 32 * i) * HIDN + kcol;
    const float* brp[2];
#pragma unroll
    for (int i = 0; i < 2; i++)
        brp[i] = W + (size_t)(n0 + ldrow + 32 * i) * HIDN + kcol;

    float4 areg[4], breg[2];
    float acc[4][4][4];
#pragma unroll
    for (int a = 0; a < 4; a++)
#pragma unroll
        for (int b_ = 0; b_ < 4; b_++)
#pragma unroll
            for (int c_ = 0; c_ < 4; c_++) acc[a][b_][c_] = 0.f;

#pragma unroll
    for (int i = 0; i < 4; i++) areg[i] = *(const float4*)(arp[i]);
#pragma unroll
    for (int i = 0; i < 2; i++) breg[i] = *(const float4*)(brp[i]);
#pragma unroll
    for (int i = 0; i < 4; i++) {
        float4 v = areg[i];
        v.x = f2tf32(v.x); v.y = f2tf32(v.y); v.z = f2tf32(v.z); v.w = f2tf32(v.w);
        *(float4*)&sm.A[0][(ldrow + 32 * i) * AS + kcol] = v;
    }
#pragma unroll
    for (int i = 0; i < 2; i++) {
        float4 v = breg[i];
        v.x = f2tf32(v.x); v.y = f2tf32(v.y); v.z = f2tf32(v.z); v.w = f2tf32(v.w);
        *(float4*)&sm.B[0][(ldrow + 32 * i) * BSS + kcol] = v;
    }
    __syncthreads();

    const int NCH = HIDN / BK;
    for (int kc = 0; kc < NCH; kc++) {
        int cur = kc & 1;
        if (kc + 1 < NCH) {
#pragma unroll
            for (int i = 0; i < 4; i++) areg[i] = *(const float4*)(arp[i] + (kc + 1) * BK);
#pragma unroll
            for (int i = 0; i < 2; i++) breg[i] = *(const float4*)(brp[i] + (kc + 1) * BK);
        }
#pragma unroll
        for (int k8 = 0; k8 < BK; k8 += 8) {
            uint32_t af[4][4], bfr[4][2];
#pragma unroll
            for (int mt = 0; mt < 4; mt++) {
                const float* ap = &sm.A[cur][(wm + mt * 16 + (lane >> 2)) * AS + k8 + (lane & 3)];
                af[mt][0] = __float_as_uint(ap[0]);
                af[mt][1] = __float_as_uint(ap[8 * AS]);
                af[mt][2] = __float_as_uint(ap[4]);
                af[mt][3] = __float_as_uint(ap[8 * AS + 4]);
            }
#pragma unroll
            for (int nt = 0; nt < 4; nt++) {
                const float* bp = &sm.B[cur][(wn + nt * 8 + (lane >> 2)) * BSS + k8 + (lane & 3)];
                bfr[nt][0] = __float_as_uint(bp[0]);
                bfr[nt][1] = __float_as_uint(bp[4]);
            }
#pragma unroll
            for (int mt = 0; mt < 4; mt++)
#pragma unroll
                for (int nt = 0; nt < 4; nt++)
                    asm volatile(
                        "mma.sync.aligned.m16n8k8.row.col.f32.tf32.tf32.f32 "
                        "{%0,%1,%2,%3}, {%4,%5,%6,%7}, {%8,%9}, {%0,%1,%2,%3};"
                        : "+f"(acc[mt][nt][0]), "+f"(acc[mt][nt][1]),
                          "+f"(acc[mt][nt][2]), "+f"(acc[mt][nt][3])
                        : "r"(af[mt][0]), "r"(af[mt][1]), "r"(af[mt][2]), "r"(af[mt][3]),
                          "r"(bfr[nt][0]), "r"(bfr[nt][1]));
        }
        if (kc + 1 < NCH) {
            int nxt = cur ^ 1;
#pragma unroll
            for (int i = 0; i < 4; i++) {
                float4 v = areg[i];
                v.x = f2tf32(v.x); v.y = f2tf32(v.y); v.z = f2tf32(v.z); v.w = f2tf32(v.w);
                *(float4*)&sm.A[nxt][(ldrow + 32 * i) * AS + kcol] = v;
            }
#pragma unroll
            for (int i = 0; i < 2; i++) {
                float4 v = breg[i];
                v.x = f2tf32(v.x); v.y = f2tf32(v.y); v.z = f2tf32(v.z); v.w = f2tf32(v.w);
                *(float4*)&sm.B[nxt][(ldrow + 32 * i) * BSS + kcol] = v;
            }
        }
        __syncthreads();
    }

#pragma unroll
    for (int mt = 0; mt < 4; mt++) {
#pragma unroll
        for (int nt = 0; nt < 4; nt++) {
            int r = m0 + wm + mt * 16 + (lane >> 2);
            int cidx = n0 + wn + nt * 8 + (lane & 3) * 2;
            float2 bv = *(const float2*)&biasp[cidx];
            float2 v0; v0.x = acc[mt][nt][0] + bv.x; v0.y = acc[mt][nt][1] + bv.y;
            float2 v1; v1.x = acc[mt][nt][2] + bv.x; v1.y = acc[mt][nt][3] + bv.y;
            *(float2*)&Cout[(size_t)r * NCLS + cidx] = v0;
            *(float2*)&Cout[(size_t)(r + 8) * NCLS + cidx] = v1;
        }
    }
}

// ---------------- launch ----------------
extern "C" void kernel_launch(void* const* d_in, const int* in_sizes, int n_in,
                              void* d_out, int out_size)
{
    const int*   X   = (const int*)  d_in[0];
    const float* h0  = (const float*)d_in[1];
    const float* c0  = (const float*)d_in[2];
    const float* emb = (const float*)d_in[3];
    const float* Ui  = (const float*)d_in[4];
    const float* Vi  = (const float*)d_in[5];
    const float* bi  = (const float*)d_in[6];
    const float* Uf  = (const float*)d_in[7];
    const float* Vf  = (const float*)d_in[8];
    const float* bf  = (const float*)d_in[9];
    const float* Uc  = (const float*)d_in[10];
    const float* Vc  = (const float*)d_in[11];
    const float* bc  = (const float*)d_in[12];
    const float* Uo  = (const float*)d_in[13];
    const float* Vo  = (const float*)d_in[14];
    const float* bo  = (const float*)d_in[15];
    const float* W   = (const float*)d_in[16];
    const float* b   = (const float*)d_in[17];
    float* out = (float*)d_out;

    cudaFuncSetAttribute(lstm_persistent_kernel,
                         cudaFuncAttributeMaxDynamicSharedMemorySize, SMEM_P_BYTES);
    cudaFuncSetAttribute(input_gemm_kernel,
                         cudaFuncAttributeMaxDynamicSharedMemorySize, IG_SMEM_B);

    // 1) pack weights (bf16 interleaved), biases, init state, reset barriers
    pack_kernel<<<(NG * (HIDN / 2) + 255) / 256, 256>>>(Ui, Vi, bi, Uf, Vf, bf,
                                                        Uc, Vc, bc, Uo, Vo, bo, h0, c0);
    pack_emb_kernel<<<(int)(((size_t)NCLS * (EMBD / 2) + 255) / 256), 256>>>(emb);

    // 2) all input-side gate preactivations (cp.async 3-stage, ldmatrix)
    input_gemm_kernel<<<dim3(NG / 128, (SEQL * BATCH) / 128), 256, IG_SMEM_B>>>(X);

    // 3) all 128 recurrent steps (V resident, split-K with DECOUPLED named-barrier groups)
    lstm_persistent_kernel<<<NCTA, PTHREADS, SMEM_P_BYTES>>>();

    // 4) output projection (tf32): out = h_final @ W^T + b
    out_gemm_kernel<<<dim3(NCLS / BN, BATCH / BM), 128>>>(W, b, out);
}

// round 16
// speedup vs baseline: 1.4175x; 1.0205x over previous
#include <cuda_runtime.h>
#include <cuda_bf16.h>
#include <cstdint>
#include <cmath>

#define HIDN 1024
#define EMBD 1024
#define BATCH 256
#define SEQL 128
#define NCLS 32000
#define NG   4096   /* 4*HIDN, gate-interleaved: n = 4*j + g */

#define BM 128
#define BN 64
#define BK 16
#define AS 20
#define BSS 20
#define GS 68
#define VSTR 516
#define ASTR 36          /* stage stride (u32), conflict-free for ldmatrix */
#define STG_A (128 * ASTR)

#define NCTA 128
#define PTHREADS 256

// input-GEMM cp.async pipeline geometry
#define IG_STAGE_U32 (2 * 128 * ASTR)
#define IG_STAGE_B   (IG_STAGE_U32 * 4)
#define IG_BOFF_B    (128 * ASTR * 4)
#define IG_SMEM_B    (3 * IG_STAGE_B)

// steps kernel smem: V resident + 2 staging buffers; G tile overlays staging
#define SMEM_P_BYTES ((64 * VSTR) * 4 + 2 * STG_A * 4)

// ---------------- device scratch (no allocations allowed) ----------------
static __device__ unsigned g_Ub[NG * (HIDN / 2)];            // 8 MB interleaved U, bf16x2
static __device__ unsigned g_Vb[NG * (HIDN / 2)];            // 8 MB interleaved V, bf16x2
static __device__ unsigned g_Eb[(size_t)NCLS * (EMBD / 2)];  // 64 MB emb, bf16x2
static __device__ float    g_ball[NG];
static __device__ unsigned g_Zinb[(size_t)SEQL * BATCH * (NG / 2)]; // 256 MB Zin, bf16x2
static __device__ float    g_h[2][BATCH * HIDN];             // fp32 h (final proj reads [0])
static __device__ unsigned g_hb[2][BATCH * (HIDN / 2)];      // bf16x2 h ping-pong
static __device__ float    g_c[BATCH * HIDN];
static __device__ unsigned g_barA[32];                       // 2 barrier counters (slots 0,16)

// ---------------- helpers ----------------
__device__ __forceinline__ float f2tf32(float x) {
    uint32_t r;
    asm("cvt.rna.tf32.f32 %0, %1;" : "=r"(r) : "f"(x));
    return __uint_as_float(r);
}
__device__ __forceinline__ unsigned pack_bf2(float a, float b) {
    __nv_bfloat162 v = __floats2bfloat162_rn(a, b);
    return *reinterpret_cast<unsigned*>(&v);
}
__device__ __forceinline__ float2 unpack_bf2(unsigned u) {
    __nv_bfloat162 v = *reinterpret_cast<__nv_bfloat162*>(&u);
    return __bfloat1622float2(v);
}
__device__ __forceinline__ float fsig(float x) {
    return __fdividef(1.f, 1.f + __expf(-x));
}
__device__ __forceinline__ float ftanh(float x) {
    return __fdividef(2.f, 1.f + __expf(-2.f * x)) - 1.f;
}
__device__ __forceinline__ void mma_bf16(float* acc, const unsigned* a, const unsigned* b) {
    asm volatile(
        "mma.sync.aligned.m16n8k16.row.col.f32.bf16.bf16.f32 "
        "{%0,%1,%2,%3}, {%4,%5,%6,%7}, {%8,%9}, {%0,%1,%2,%3};"
        : "+f"(acc[0]), "+f"(acc[1]), "+f"(acc[2]), "+f"(acc[3])
        : "r"(a[0]), "r"(a[1]), "r"(a[2]), "r"(a[3]), "r"(b[0]), "r"(b[1]));
}
__device__ __forceinline__ uint32_t smem_u32(const void* p) {
    uint32_t a;
    asm("{ .reg .u64 t; cvta.to.shared.u64 t, %1; cvt.u32.u64 %0, t; }" : "=r"(a) : "l"(p));
    return a;
}
#define LDSM_X4(r0, r1, r2, r3, addr) \
    asm volatile("ldmatrix.sync.aligned.m8n8.x4.shared.b16 {%0,%1,%2,%3}, [%4];" \
                 : "=r"(r0), "=r"(r1), "=r"(r2), "=r"(r3) : "r"(addr))
#define CP_ASYNC16(dst, src) \
    asm volatile("cp.async.cg.shared.global [%0], [%1], 16;" :: "r"(dst), "l"(src))
#define CP_COMMIT() asm volatile("cp.async.commit_group;" ::: "memory")
#define CP_WAIT1()  asm volatile("cp.async.wait_group 1;" ::: "memory")

// ---------------- pack: interleave U/V (bf16), biases, init state ----------------
__global__ void pack_kernel(const float* __restrict__ Ui, const float* __restrict__ Vi, const float* __restrict__ bi,
                            const float* __restrict__ Uf, const float* __restrict__ Vf, const float* __restrict__ bf,
                            const float* __restrict__ Uc, const float* __restrict__ Vc, const float* __restrict__ bc,
                            const float* __restrict__ Uo, const float* __restrict__ Vo, const float* __restrict__ bo,
                            const float* __restrict__ h0, const float* __restrict__ c0)
{
    int idx = blockIdx.x * blockDim.x + threadIdx.x;
    if (idx >= NG * (HIDN / 2)) return;
    if (idx < 32) g_barA[idx] = 0u;
    int n = idx >> 9;
    int k2 = idx & 511;
    int j = n >> 2, g = n & 3;
    const float *U, *V, *bb;
    if (g == 0)      { U = Ui; V = Vi; bb = bi; }
    else if (g == 1) { U = Uf; V = Vf; bb = bf; }
    else if (g == 2) { U = Uc; V = Vc; bb = bc; }
    else             { U = Uo; V = Vo; bb = bo; }
    const float* Up = U + (size_t)j * HIDN + 2 * k2;
    const float* Vp = V + (size_t)j * HIDN + 2 * k2;
    g_Ub[idx] = pack_bf2(Up[0], Up[1]);
    g_Vb[idx] = pack_bf2(Vp[0], Vp[1]);
    if (k2 == 0) g_ball[n] = bb[j];
    if (idx < BATCH * (HIDN / 2)) {
        g_hb[0][idx] = pack_bf2(h0[2 * idx], h0[2 * idx + 1]);
        float2 hv; hv.x = h0[2 * idx]; hv.y = h0[2 * idx + 1];
        *(float2*)&g_h[0][2 * idx] = hv;
        float2 cv; cv.x = c0[2 * idx]; cv.y = c0[2 * idx + 1];
        *(float2*)&g_c[2 * idx] = cv;
    }
}

__global__ void pack_emb_kernel(const float* __restrict__ emb)
{
    size_t idx = (size_t)blockIdx.x * blockDim.x + threadIdx.x;
    if (idx >= (size_t)NCLS * (EMBD / 2)) return;
    g_Eb[idx] = pack_bf2(emb[2 * idx], emb[2 * idx + 1]);
}

// ---------------- bf16 input GEMM: Zin = gather(emb,X) @ Uall^T + ball (bf16 out) --------
__global__ __launch_bounds__(256, 2)
void input_gemm_kernel(const int* __restrict__ Xids)
{
    extern __shared__ unsigned igsm[];
    __shared__ int vrow[128];

    const int tid  = threadIdx.x;
    const int lane = tid & 31;
    const int warp = tid >> 5;
    const int wm = (warp >> 2) * 64;
    const int wn = (warp & 3) * 32;
    const int n0 = blockIdx.x * 128;
    const int m0 = blockIdx.y * 128;

    if (tid < 128) {
        int r = m0 + tid;
        vrow[tid] = Xids[(r & 255) * SEQL + (r >> 8)];
    }
    __syncthreads();

    const uint32_t sbase = smem_u32(igsm);

    const unsigned* srcA[4];
    const unsigned* srcB[4];
    uint32_t dstoff[4];
#pragma unroll
    for (int i = 0; i < 4; i++) {
        int idx = tid + i * 256;
        int row = idx >> 3, cb = idx & 7;
        srcA[i] = g_Eb + (size_t)vrow[row] * 512 + cb * 4;
        srcB[i] = g_Ub + (size_t)(n0 + row) * 512 + cb * 4;
        dstoff[i] = (uint32_t)(row * ASTR + cb * 4) * 4;
    }

    uint32_t aoff[4];
#pragma unroll
    for (int mt = 0; mt < 4; mt++)
        aoff[mt] = (uint32_t)(wm + mt * 16 + (lane & 7) + ((lane >> 3) & 1) * 8) * ASTR
                 + ((lane >> 4) & 1) * 4;
    uint32_t boff[2];
#pragma unroll
    for (int p = 0; p < 2; p++)
        boff[p] = (uint32_t)(wn + p * 16 + (lane & 7) + ((lane >> 4) & 1) * 8) * ASTR
                + ((lane >> 3) & 1) * 4;

    float acc[4][4][4];
#pragma unroll
    for (int a = 0; a < 4; a++)
#pragma unroll
        for (int b_ = 0; b_ < 4; b_++)
#pragma unroll
            for (int c_ = 0; c_ < 4; c_++) acc[a][b_][c_] = 0.f;

    auto issue = [&](int chunk, int stage) {
        uint32_t base = sbase + (uint32_t)stage * IG_STAGE_B;
#pragma unroll
        for (int i = 0; i < 4; i++) {
            CP_ASYNC16(base + dstoff[i], srcA[i] + chunk * 32);
            CP_ASYNC16(base + IG_BOFF_B + dstoff[i], srcB[i] + chunk * 32);
        }
        CP_COMMIT();
    };

    issue(0, 0);
    issue(1, 1);

    int cur = 0, nxt = 2;
    for (int kc = 0; kc < 16; kc++) {
        CP_WAIT1();
        __syncthreads();

        const uint32_t abase = sbase + (uint32_t)cur * IG_STAGE_B;
        const uint32_t bbase = abase + IG_BOFF_B;
#pragma unroll
        for (int ks = 0; ks < 4; ks++) {
            unsigned af[4][4], bfr[4][2];
#pragma unroll
            for (int mt = 0; mt < 4; mt++)
                LDSM_X4(af[mt][0], af[mt][1], af[mt][2], af[mt][3],
                        abase + (aoff[mt] + ks * 8) * 4);
#pragma unroll
            for (int p = 0; p < 2; p++)
                LDSM_X4(bfr[2 * p][0], bfr[2 * p][1], bfr[2 * p + 1][0], bfr[2 * p + 1][1],
                        bbase + (boff[p] + ks * 8) * 4);
#pragma unroll
            for (int mt = 0; mt < 4; mt++)
#pragma unroll
                for (int nt = 0; nt < 4; nt++)
                    mma_bf16(acc[mt][nt], af[mt], bfr[nt]);
        }
        if (kc + 2 < 16) issue(kc + 2, nxt);
        else CP_COMMIT();
        cur = (cur == 2) ? 0 : cur + 1;
        nxt = (nxt == 2) ? 0 : nxt + 1;
    }

    // epilogue: + bias, pack to bf16x2, store
#pragma unroll
    for (int mt = 0; mt < 4; mt++) {
#pragma unroll
        for (int nt = 0; nt < 4; nt++) {
            int r = m0 + wm + mt * 16 + (lane >> 2);
            int cidx = n0 + wn + nt * 8 + (lane & 3) * 2;   // even
            float2 bv = *(const float2*)&g_ball[cidx];
            unsigned p0 = pack_bf2(acc[mt][nt][0] + bv.x, acc[mt][nt][1] + bv.y);
            unsigned p1 = pack_bf2(acc[mt][nt][2] + bv.x, acc[mt][nt][3] + bv.y);
            g_Zinb[(size_t)r * (NG / 2) + (cidx >> 1)] = p0;
            g_Zinb[(size_t)(r + 8) * (NG / 2) + (cidx >> 1)] = p1;
        }
    }
}

// ---------------- persistent recurrent kernel (R10 GEMM loop, bf16 Zin, fast tanh) -------
__global__ __launch_bounds__(PTHREADS, 1)
void lstm_persistent_kernel()
{
    extern __shared__ unsigned smem[];
    unsigned* smV = smem;
    unsigned* smA = smem + 64 * VSTR;
    float*    smG = (float*)(smem + 64 * VSTR);

    const int tid  = threadIdx.x;
    const int lane = tid & 31;
    const int warp = tid >> 5;
    const int wm = (warp >> 1) * 32;
    const int wn = (warp & 1) * 32;
    const int bid = blockIdx.x;
    const int m0  = (bid & 1) * 128;
    const int nsl = bid >> 1;
    const int n0  = nsl * 64;
    unsigned* bar = &g_barA[(bid & 1) * 16];

    for (int i = tid; i < 64 * 128; i += PTHREADS) {
        int n = i >> 7, k4 = (i & 127) * 4;
        *(uint4*)&smV[n * VSTR + k4] = *(const uint4*)&g_Vb[(size_t)(n0 + n) * 512 + k4];
    }

    float creg[4][2];
#pragma unroll
    for (int it = 0; it < 4; it++) {
        int idx = tid + it * PTHREADS;
        int lr = idx >> 3, jp = idx & 7;
        float2 cv = *(const float2*)&g_c[(m0 + lr) * HIDN + nsl * 16 + jp * 2];
        creg[it][0] = cv.x; creg[it][1] = cv.y;
    }

    const uint32_t smA_u = smem_u32(smA);
    const uint32_t smV_u = smem_u32(smV);

    uint32_t aoff[2];
#pragma unroll
    for (int mt = 0; mt < 2; mt++)
        aoff[mt] = (uint32_t)(wm + mt * 16 + (lane & 7) + ((lane >> 3) & 1) * 8) * ASTR
                 + ((lane >> 4) & 1) * 4;
    uint32_t voff[2];
#pragma unroll
    for (int p = 0; p < 2; p++)
        voff[p] = (uint32_t)(wn + p * 16 + (lane & 7) + ((lane >> 4) & 1) * 8) * VSTR
                + ((lane >> 3) & 1) * 4;

    const int kcol  = (tid & 3) * 4;
    const int ldrow = tid >> 2;

    // Zin prefetch thread mapping (it-invariant jp); 8 gates = one uint4 of bf16x2
    const int zlr0 = tid >> 3, zjp = tid & 7;

    // prefetch Zin for step 0
    uint4 zpre[4];
#pragma unroll
    for (int it = 0; it < 4; it++) {
        size_t zb = ((size_t)(m0 + zlr0 + it * 32)) * (NG / 2) + (n0 >> 1) + zjp * 4;
        zpre[it] = *(const uint4*)&g_Zinb[zb];
    }
    __syncthreads();

    for (int t = 0; t < SEQL; t++) {
        const unsigned* hin = g_hb[t & 1];
        const unsigned* arp0 = hin + (size_t)(m0 + ldrow) * 512 + kcol;
        const unsigned* arp1 = hin + (size_t)(m0 + ldrow + 64) * 512 + kcol;

        float acc[2][4][4];
#pragma unroll
        for (int a = 0; a < 2; a++)
#pragma unroll
            for (int b_ = 0; b_ < 4; b_++)
#pragma unroll
                for (int c_ = 0; c_ < 4; c_++) acc[a][b_][c_] = 0.f;

        // K-chunk = 32 half2 (R10 structure): two uint4 per row per chunk
        uint4 a00 = *(const uint4*)arp0;
        uint4 a01 = *(const uint4*)(arp0 + 16);
        uint4 a10 = *(const uint4*)arp1;
        uint4 a11 = *(const uint4*)(arp1 + 16);
        *(uint4*)&smA[ldrow * ASTR + kcol]             = a00;
        *(uint4*)&smA[ldrow * ASTR + kcol + 16]        = a01;
        *(uint4*)&smA[(ldrow + 64) * ASTR + kcol]      = a10;
        *(uint4*)&smA[(ldrow + 64) * ASTR + kcol + 16] = a11;
        __syncthreads();

        for (int kc = 0; kc < 16; kc++) {
            const int cur = kc & 1;
            if (kc + 1 < 16) {
                a00 = *(const uint4*)(arp0 + (kc + 1) * 32);
                a01 = *(const uint4*)(arp0 + (kc + 1) * 32 + 16);
                a10 = *(const uint4*)(arp1 + (kc + 1) * 32);
                a11 = *(const uint4*)(arp1 + (kc + 1) * 32 + 16);
            }
            const uint32_t abase = smA_u + (uint32_t)cur * (STG_A * 4);
            const uint32_t vbase = smV_u + (uint32_t)(kc * 32) * 4;
#pragma unroll
            for (int ks = 0; ks < 4; ks++) {
                unsigned af[2][4], bfr[4][2];
#pragma unroll
                for (int mtw = 0; mtw < 2; mtw++)
                    LDSM_X4(af[mtw][0], af[mtw][1], af[mtw][2], af[mtw][3],
                            abase + (aoff[mtw] + ks * 8) * 4);
#pragma unroll
                for (int p = 0; p < 2; p++)
                    LDSM_X4(bfr[2 * p][0], bfr[2 * p][1], bfr[2 * p + 1][0], bfr[2 * p + 1][1],
                            vbase + (voff[p] + ks * 8) * 4);
#pragma unroll
                for (int mtw = 0; mtw < 2; mtw++)
#pragma unroll
                    for (int ntw = 0; ntw < 4; ntw++)
                        mma_bf16(acc[mtw][ntw], af[mtw], bfr[ntw]);
            }
            if (kc + 1 < 16) {
                unsigned* Ad = smA + ((kc + 1) & 1) * STG_A;
                *(uint4*)&Ad[ldrow * ASTR + kcol]             = a00;
                *(uint4*)&Ad[ldrow * ASTR + kcol + 16]        = a01;
                *(uint4*)&Ad[(ldrow + 64) * ASTR + kcol]      = a10;
                *(uint4*)&Ad[(ldrow + 64) * ASTR + kcol + 16] = a11;
            }
            __syncthreads();
        }

        // accum -> smem gate tile (overlays A staging; all mma reads done)
#pragma unroll
        for (int mtw = 0; mtw < 2; mtw++)
#pragma unroll
            for (int ntw = 0; ntw < 4; ntw++) {
                int lr = wm + mtw * 16 + (lane >> 2);
                int lc = wn + ntw * 8 + (lane & 3) * 2;
                smG[lr * GS + lc]           = acc[mtw][ntw][0];
                smG[lr * GS + lc + 1]       = acc[mtw][ntw][1];
                smG[(lr + 8) * GS + lc]     = acc[mtw][ntw][2];
                smG[(lr + 8) * GS + lc + 1] = acc[mtw][ntw][3];
            }
        __syncthreads();

        // fused LSTM cell (c in registers)
        unsigned* hbout = g_hb[(t & 1) ^ 1];
#pragma unroll
        for (int it = 0; it < 4; it++) {
            int lr = zlr0 + it * 32;
            int m = m0 + lr;
            float2 za  = unpack_bf2(zpre[it].x);
            float2 zb2 = unpack_bf2(zpre[it].y);
            float2 zc  = unpack_bf2(zpre[it].z);
            float2 zd  = unpack_bf2(zpre[it].w);
            const float* Gp = &smG[lr * GS + zjp * 8];

            float i0 = fsig(Gp[0] + za.x);
            float f0 = fsig(Gp[1] + za.y);
            float g0 = ftanh(Gp[2] + zb2.x);
            float o0 = fsig(Gp[3] + zb2.y);
            float i1 = fsig(Gp[4] + zc.x);
            float f1 = fsig(Gp[5] + zc.y);
            float g1 = ftanh(Gp[6] + zd.x);
            float o1 = fsig(Gp[7] + zd.y);

            float cn0 = f0 * creg[it][0] + i0 * g0;
            float cn1 = f1 * creg[it][1] + i1 * g1;
            creg[it][0] = cn0; creg[it][1] = cn1;

            float h0v = o0 * ftanh(cn0);
            float h1v = o1 * ftanh(cn1);
            hbout[m * 512 + nsl * 8 + zjp] = pack_bf2(h0v, h1v);
            if (t == SEQL - 1) {
                float2 hf; hf.x = h0v; hf.y = h1v;
                *(float2*)&g_h[0][m * HIDN + nsl * 16 + zjp * 2] = hf;
            }
        }

        if (t < SEQL - 1) {
            // prefetch next step's Zin BEFORE the barrier (static data)
#pragma unroll
            for (int it = 0; it < 4; it++) {
                size_t zb = ((size_t)(t + 1) * BATCH + m0 + zlr0 + it * 32) * (NG / 2)
                          + (n0 >> 1) + zjp * 4;
                zpre[it] = *(const uint4*)&g_Zinb[zb];
            }
            __syncthreads();
            if (tid == 0) {
                __threadfence();
                atomicAdd(bar, 1u);
                const unsigned target = 64u * (t + 1);
                unsigned v;
                do {
                    asm volatile("ld.acquire.gpu.u32 %0, [%1];"
                                 : "=r"(v) : "l"(bar) : "memory");
                } while (v < target);
            }
            __syncthreads();
        }
    }
}

// ---------------- tf32 output projection: out = h_final @ W^T + b ----------------
__global__ __launch_bounds__(128)
void out_gemm_kernel(const float* __restrict__ W,
                     const float* __restrict__ biasp,
                     float* __restrict__ Cout)
{
    const int tid  = threadIdx.x;
    const int lane = tid & 31;
    const int warp = tid >> 5;
    const int wm = (warp >> 1) * 64;
    const int wn = (warp & 1) * 32;
    const int n0 = blockIdx.x * BN;
    const int m0 = blockIdx.y * BM;

    __shared__ struct { float A[2][BM * AS]; float B[2][BN * BSS]; } sm;

    const float* Ain = g_h[0];
    const int kcol  = (tid & 3) * 4;
    const int ldrow = tid >> 2;

    const float* arp[4];
#pragma unroll
    for (int i = 0; i < 4; i++)
        arp[i] = Ain + (size_t)(m0 + ldrow + 32 * i) * HIDN + kcol;
    const float* brp[2];
#pragma unroll
    for (int i = 0; i < 2; i++)
        brp[i] = W + (size_t)(n0 + ldrow + 32 * i) * HIDN + kcol;

    float4 areg[4], breg[2];
    float acc[4][4][4];
#pragma unroll
    for (int a = 0; a < 4; a++)
#pragma unroll
        for (int b_ = 0; b_ < 4; b_++)
#pragma unroll
            for (int c_ = 0; c_ < 4; c_++) acc[a][b_][c_] = 0.f;

#pragma unroll
    for (int i = 0; i < 4; i++) areg[i] = *(const float4*)(arp[i]);
#pragma unroll
    for (int i = 0; i < 2; i++) breg[i] = *(const float4*)(brp[i]);
#pragma unroll
    for (int i = 0; i < 4; i++) {
        float4 v = areg[i];
        v.x = f2tf32(v.x); v.y = f2tf32(v.y); v.z = f2tf32(v.z); v.w = f2tf32(v.w);
        *(float4*)&sm.A[0][(ldrow + 32 * i) * AS + kcol] = v;
    }
#pragma unroll
    for (int i = 0; i < 2; i++) {
        float4 v = breg[i];
        v.x = f2tf32(v.x); v.y = f2tf32(v.y); v.z = f2tf32(v.z); v.w = f2tf32(v.w);
        *(float4*)&sm.B[0][(ldrow + 32 * i) * BSS + kcol] = v;
    }
    __syncthreads();

    const int NCH = HIDN / BK;
    for (int kc = 0; kc < NCH; kc++) {
        int cur = kc & 1;
        if (kc + 1 < NCH) {
#pragma unroll
            for (int i = 0; i < 4; i++) areg[i] = *(const float4*)(arp[i] + (kc + 1) * BK);
#pragma unroll
            for (int i = 0; i < 2; i++) breg[i] = *(const float4*)(brp[i] + (kc + 1) * BK);
        }
#pragma unroll
        for (int k8 = 0; k8 < BK; k8 += 8) {
            uint32_t af[4][4], bfr[4][2];
#pragma unroll
            for (int mt = 0; mt < 4; mt++) {
                const float* ap = &sm.A[cur][(wm + mt * 16 + (lane >> 2)) * AS + k8 + (lane & 3)];
                af[mt][0] = __float_as_uint(ap[0]);
                af[mt][1] = __float_as_uint(ap[8 * AS]);
                af[mt][2] = __float_as_uint(ap[4]);
                af[mt][3] = __float_as_uint(ap[8 * AS + 4]);
            }
#pragma unroll
            for (int nt = 0; nt < 4; nt++) {
                const float* bp = &sm.B[cur][(wn + nt * 8 + (lane >> 2)) * BSS + k8 + (lane & 3)];
                bfr[nt][0] = __float_as_uint(bp[0]);
                bfr[nt][1] = __float_as_uint(bp[4]);
            }
#pragma unroll
            for (int mt = 0; mt < 4; mt++)
#pragma unroll
                for (int nt = 0; nt < 4; nt++)
                    asm volatile(
                        "mma.sync.aligned.m16n8k8.row.col.f32.tf32.tf32.f32 "
                        "{%0,%1,%2,%3}, {%4,%5,%6,%7}, {%8,%9}, {%0,%1,%2,%3};"
                        : "+f"(acc[mt][nt][0]), "+f"(acc[mt][nt][1]),
                          "+f"(acc[mt][nt][2]), "+f"(acc[mt][nt][3])
                        : "r"(af[mt][0]), "r"(af[mt][1]), "r"(af[mt][2]), "r"(af[mt][3]),
                          "r"(bfr[nt][0]), "r"(bfr[nt][1]));
        }
        if (kc + 1 < NCH) {
            int nxt = cur ^ 1;
#pragma unroll
            for (int i = 0; i < 4; i++) {
                float4 v = areg[i];
                v.x = f2tf32(v.x); v.y = f2tf32(v.y); v.z = f2tf32(v.z); v.w = f2tf32(v.w);
                *(float4*)&sm.A[nxt][(ldrow + 32 * i) * AS + kcol] = v;
            }
#pragma unroll
            for (int i = 0; i < 2; i++) {
                float4 v = breg[i];
                v.x = f2tf32(v.x); v.y = f2tf32(v.y); v.z = f2tf32(v.z); v.w = f2tf32(v.w);
                *(float4*)&sm.B[nxt][(ldrow + 32 * i) * BSS + kcol] = v;
            }
        }
        __syncthreads();
    }

#pragma unroll
    for (int mt = 0; mt < 4; mt++) {
#pragma unroll
        for (int nt = 0; nt < 4; nt++) {
            int r = m0 + wm + mt * 16 + (lane >> 2);
            int cidx = n0 + wn + nt * 8 + (lane & 3) * 2;
            float2 bv = *(const float2*)&biasp[cidx];
            float2 v0; v0.x = acc[mt][nt][0] + bv.x; v0.y = acc[mt][nt][1] + bv.y;
            float2 v1; v1.x = acc[mt][nt][2] + bv.x; v1.y = acc[mt][nt][3] + bv.y;
            *(float2*)&Cout[(size_t)r * NCLS + cidx] = v0;
            *(float2*)&Cout[(size_t)(r + 8) * NCLS + cidx] = v1;
        }
    }
}

// ---------------- launch ----------------
extern "C" void kernel_launch(void* const* d_in, const int* in_sizes, int n_in,
                              void* d_out, int out_size)
{
    const int*   X   = (const int*)  d_in[0];
    const float* h0  = (const float*)d_in[1];
    const float* c0  = (const float*)d_in[2];
    const float* emb = (const float*)d_in[3];
    const float* Ui  = (const float*)d_in[4];
    const float* Vi  = (const float*)d_in[5];
    const float* bi  = (const float*)d_in[6];
    const float* Uf  = (const float*)d_in[7];
    const float* Vf  = (const float*)d_in[8];
    const float* bf  = (const float*)d_in[9];
    const float* Uc  = (const float*)d_in[10];
    const float* Vc  = (const float*)d_in[11];
    const float* bc  = (const float*)d_in[12];
    const float* Uo  = (const float*)d_in[13];
    const float* Vo  = (const float*)d_in[14];
    const float* bo  = (const float*)d_in[15];
    const float* W   = (const float*)d_in[16];
    const float* b   = (const float*)d_in[17];
    float* out = (float*)d_out;

    cudaFuncSetAttribute(lstm_persistent_kernel,
                         cudaFuncAttributeMaxDynamicSharedMemorySize, SMEM_P_BYTES);
    cudaFuncSetAttribute(input_gemm_kernel,
                         cudaFuncAttributeMaxDynamicSharedMemorySize, IG_SMEM_B);

    // 1) pack weights (bf16 interleaved), biases, init state, reset barriers
    pack_kernel<<<(NG * (HIDN / 2) + 255) / 256, 256>>>(Ui, Vi, bi, Uf, Vf, bf,
                                                        Uc, Vc, bc, Uo, Vo, bo, h0, c0);
    pack_emb_kernel<<<(int)(((size_t)NCLS * (EMBD / 2) + 255) / 256), 256>>>(emb);

    // 2) all input-side gate preactivations (cp.async 3-stage, ldmatrix, bf16 Zin)
    input_gemm_kernel<<<dim3(NG / 128, (SEQL * BATCH) / 128), 256, IG_SMEM_B>>>(X);

    // 3) all 128 recurrent steps in ONE persistent kernel (V resident, split barriers)
    lstm_persistent_kernel<<<NCTA, PTHREADS, SMEM_P_BYTES>>>();

    // 4) output projection (tf32): out = h_final @ W^T + b
    out_gemm_kernel<<<dim3(NCLS / BN, BATCH / BM), 128>>>(W, b, out);
}

// round 17
// speedup vs baseline: 1.6086x; 1.1348x over previous
#include <cuda_runtime.h>
#include <cuda_bf16.h>
#include <cstdint>
#include <cmath>

#define HIDN 1024
#define EMBD 1024
#define BATCH 256
#define SEQL 128
#define NCLS 32000
#define NG   4096   /* 4*HIDN, gate-interleaved: n = 4*j + g */

#define BM 128
#define BN 64
#define BK 16
#define AS 20
#define BSS 20
#define GS 68
#define VSTR 516
#define ASTR 36          /* stage stride (u32), conflict-free for ldmatrix */
#define STG_A (128 * ASTR)

#define NCTA 128
#define PTHREADS 256

// input-GEMM cp.async pipeline geometry
#define IG_STAGE_U32 (2 * 128 * ASTR)
#define IG_STAGE_B   (IG_STAGE_U32 * 4)
#define IG_BOFF_B    (128 * ASTR * 4)
#define IG_SMEM_B    (3 * IG_STAGE_B)

// steps kernel smem: V resident + 3 cp.async stage buffers; G tile overlays staging
#define SMEM_P_BYTES ((64 * VSTR) * 4 + 3 * STG_A * 4)   /* 132096 + 55296 = 187392 */

// ---------------- device scratch (no allocations allowed) ----------------
static __device__ unsigned g_Ub[NG * (HIDN / 2)];            // 8 MB interleaved U, bf16x2
static __device__ unsigned g_Vb[NG * (HIDN / 2)];            // 8 MB interleaved V, bf16x2
static __device__ unsigned g_Eb[(size_t)NCLS * (EMBD / 2)];  // 64 MB emb, bf16x2
static __device__ float    g_ball[NG];
static __device__ unsigned g_Zinb[(size_t)SEQL * BATCH * (NG / 2)]; // 256 MB Zin, bf16x2
static __device__ float    g_h[2][BATCH * HIDN];             // fp32 h (final proj reads [0])
static __device__ unsigned g_hb[2][BATCH * (HIDN / 2)];      // bf16x2 h ping-pong
static __device__ float    g_c[BATCH * HIDN];
static __device__ unsigned g_barA[32];                       // 2 barrier counters (slots 0,16)

// ---------------- helpers ----------------
__device__ __forceinline__ float f2tf32(float x) {
    uint32_t r;
    asm("cvt.rna.tf32.f32 %0, %1;" : "=r"(r) : "f"(x));
    return __uint_as_float(r);
}
__device__ __forceinline__ unsigned pack_bf2(float a, float b) {
    __nv_bfloat162 v = __floats2bfloat162_rn(a, b);
    return *reinterpret_cast<unsigned*>(&v);
}
__device__ __forceinline__ float2 unpack_bf2(unsigned u) {
    __nv_bfloat162 v = *reinterpret_cast<__nv_bfloat162*>(&u);
    return __bfloat1622float2(v);
}
__device__ __forceinline__ float fsig(float x) {
    return __fdividef(1.f, 1.f + __expf(-x));
}
__device__ __forceinline__ float ftanh(float x) {
    return __fdividef(2.f, 1.f + __expf(-2.f * x)) - 1.f;
}
__device__ __forceinline__ void mma_bf16(float* acc, const unsigned* a, const unsigned* b) {
    asm volatile(
        "mma.sync.aligned.m16n8k16.row.col.f32.bf16.bf16.f32 "
        "{%0,%1,%2,%3}, {%4,%5,%6,%7}, {%8,%9}, {%0,%1,%2,%3};"
        : "+f"(acc[0]), "+f"(acc[1]), "+f"(acc[2]), "+f"(acc[3])
        : "r"(a[0]), "r"(a[1]), "r"(a[2]), "r"(a[3]), "r"(b[0]), "r"(b[1]));
}
__device__ __forceinline__ uint32_t smem_u32(const void* p) {
    uint32_t a;
    asm("{ .reg .u64 t; cvta.to.shared.u64 t, %1; cvt.u32.u64 %0, t; }" : "=r"(a) : "l"(p));
    return a;
}
#define LDSM_X4(r0, r1, r2, r3, addr) \
    asm volatile("ldmatrix.sync.aligned.m8n8.x4.shared.b16 {%0,%1,%2,%3}, [%4];" \
                 : "=r"(r0), "=r"(r1), "=r"(r2), "=r"(r3) : "r"(addr))
#define CP_ASYNC16(dst, src) \
    asm volatile("cp.async.cg.shared.global [%0], [%1], 16;" :: "r"(dst), "l"(src))
#define CP_COMMIT() asm volatile("cp.async.commit_group;" ::: "memory")
#define CP_WAIT1()  asm volatile("cp.async.wait_group 1;" ::: "memory")

// ---------------- pack: interleave U/V (bf16), biases, init state ----------------
__global__ void pack_kernel(const float* __restrict__ Ui, const float* __restrict__ Vi, const float* __restrict__ bi,
                            const float* __restrict__ Uf, const float* __restrict__ Vf, const float* __restrict__ bf,
                            const float* __restrict__ Uc, const float* __restrict__ Vc, const float* __restrict__ bc,
                            const float* __restrict__ Uo, const float* __restrict__ Vo, const float* __restrict__ bo,
                            const float* __restrict__ h0, const float* __restrict__ c0)
{
    int idx = blockIdx.x * blockDim.x + threadIdx.x;
    if (idx >= NG * (HIDN / 2)) return;
    if (idx < 32) g_barA[idx] = 0u;
    int n = idx >> 9;
    int k2 = idx & 511;
    int j = n >> 2, g = n & 3;
    const float *U, *V, *bb;
    if (g == 0)      { U = Ui; V = Vi; bb = bi; }
    else if (g == 1) { U = Uf; V = Vf; bb = bf; }
    else if (g == 2) { U = Uc; V = Vc; bb = bc; }
    else             { U = Uo; V = Vo; bb = bo; }
    const float* Up = U + (size_t)j * HIDN + 2 * k2;
    const float* Vp = V + (size_t)j * HIDN + 2 * k2;
    g_Ub[idx] = pack_bf2(Up[0], Up[1]);
    g_Vb[idx] = pack_bf2(Vp[0], Vp[1]);
    if (k2 == 0) g_ball[n] = bb[j];
    if (idx < BATCH * (HIDN / 2)) {
        g_hb[0][idx] = pack_bf2(h0[2 * idx], h0[2 * idx + 1]);
        float2 hv; hv.x = h0[2 * idx]; hv.y = h0[2 * idx + 1];
        *(float2*)&g_h[0][2 * idx] = hv;
        float2 cv; cv.x = c0[2 * idx]; cv.y = c0[2 * idx + 1];
        *(float2*)&g_c[2 * idx] = cv;
    }
}

__global__ void pack_emb_kernel(const float* __restrict__ emb)
{
    size_t idx = (size_t)blockIdx.x * blockDim.x + threadIdx.x;
    if (idx >= (size_t)NCLS * (EMBD / 2)) return;
    g_Eb[idx] = pack_bf2(emb[2 * idx], emb[2 * idx + 1]);
}

// ---------------- bf16 input GEMM: Zin = gather(emb,X) @ Uall^T + ball (bf16 out) --------
__global__ __launch_bounds__(256, 2)
void input_gemm_kernel(const int* __restrict__ Xids)
{
    extern __shared__ unsigned igsm[];
    __shared__ int vrow[128];

    const int tid  = threadIdx.x;
    const int lane = tid & 31;
    const int warp = tid >> 5;
    const int wm = (warp >> 2) * 64;
    const int wn = (warp & 3) * 32;
    const int n0 = blockIdx.x * 128;
    const int m0 = blockIdx.y * 128;

    if (tid < 128) {
        int r = m0 + tid;
        vrow[tid] = Xids[(r & 255) * SEQL + (r >> 8)];
    }
    __syncthreads();

    const uint32_t sbase = smem_u32(igsm);

    const unsigned* srcA[4];
    const unsigned* srcB[4];
    uint32_t dstoff[4];
#pragma unroll
    for (int i = 0; i < 4; i++) {
        int idx = tid + i * 256;
        int row = idx >> 3, cb = idx & 7;
        srcA[i] = g_Eb + (size_t)vrow[row] * 512 + cb * 4;
        srcB[i] = g_Ub + (size_t)(n0 + row) * 512 + cb * 4;
        dstoff[i] = (uint32_t)(row * ASTR + cb * 4) * 4;
    }

    uint32_t aoff[4];
#pragma unroll
    for (int mt = 0; mt < 4; mt++)
        aoff[mt] = (uint32_t)(wm + mt * 16 + (lane & 7) + ((lane >> 3) & 1) * 8) * ASTR
                 + ((lane >> 4) & 1) * 4;
    uint32_t boff[2];
#pragma unroll
    for (int p = 0; p < 2; p++)
        boff[p] = (uint32_t)(wn + p * 16 + (lane & 7) + ((lane >> 4) & 1) * 8) * ASTR
                + ((lane >> 3) & 1) * 4;

    float acc[4][4][4];
#pragma unroll
    for (int a = 0; a < 4; a++)
#pragma unroll
        for (int b_ = 0; b_ < 4; b_++)
#pragma unroll
            for (int c_ = 0; c_ < 4; c_++) acc[a][b_][c_] = 0.f;

    auto issue = [&](int chunk, int stage) {
        uint32_t base = sbase + (uint32_t)stage * IG_STAGE_B;
#pragma unroll
        for (int i = 0; i < 4; i++) {
            CP_ASYNC16(base + dstoff[i], srcA[i] + chunk * 32);
            CP_ASYNC16(base + IG_BOFF_B + dstoff[i], srcB[i] + chunk * 32);
        }
        CP_COMMIT();
    };

    issue(0, 0);
    issue(1, 1);

    int cur = 0, nxt = 2;
    for (int kc = 0; kc < 16; kc++) {
        CP_WAIT1();
        __syncthreads();

        const uint32_t abase = sbase + (uint32_t)cur * IG_STAGE_B;
        const uint32_t bbase = abase + IG_BOFF_B;
#pragma unroll
        for (int ks = 0; ks < 4; ks++) {
            unsigned af[4][4], bfr[4][2];
#pragma unroll
            for (int mt = 0; mt < 4; mt++)
                LDSM_X4(af[mt][0], af[mt][1], af[mt][2], af[mt][3],
                        abase + (aoff[mt] + ks * 8) * 4);
#pragma unroll
            for (int p = 0; p < 2; p++)
                LDSM_X4(bfr[2 * p][0], bfr[2 * p][1], bfr[2 * p + 1][0], bfr[2 * p + 1][1],
                        bbase + (boff[p] + ks * 8) * 4);
#pragma unroll
            for (int mt = 0; mt < 4; mt++)
#pragma unroll
                for (int nt = 0; nt < 4; nt++)
                    mma_bf16(acc[mt][nt], af[mt], bfr[nt]);
        }
        if (kc + 2 < 16) issue(kc + 2, nxt);
        else CP_COMMIT();
        cur = (cur == 2) ? 0 : cur + 1;
        nxt = (nxt == 2) ? 0 : nxt + 1;
    }

    // epilogue: + bias, pack to bf16x2, store
#pragma unroll
    for (int mt = 0; mt < 4; mt++) {
#pragma unroll
        for (int nt = 0; nt < 4; nt++) {
            int r = m0 + wm + mt * 16 + (lane >> 2);
            int cidx = n0 + wn + nt * 8 + (lane & 3) * 2;   // even
            float2 bv = *(const float2*)&g_ball[cidx];
            unsigned p0 = pack_bf2(acc[mt][nt][0] + bv.x, acc[mt][nt][1] + bv.y);
            unsigned p1 = pack_bf2(acc[mt][nt][2] + bv.x, acc[mt][nt][3] + bv.y);
            g_Zinb[(size_t)r * (NG / 2) + (cidx >> 1)] = p0;
            g_Zinb[(size_t)(r + 8) * (NG / 2) + (cidx >> 1)] = p1;
        }
    }
}

// ---------------- persistent recurrent kernel (cp.async h staging, bf16 Zin) ------------
__global__ __launch_bounds__(PTHREADS, 1)
void lstm_persistent_kernel()
{
    extern __shared__ unsigned smem[];
    unsigned* smV = smem;                        // 64 x VSTR
    unsigned* smA = smem + 64 * VSTR;            // 3 x STG_A cp.async stages
    float*    smG = (float*)smA;                 // G tile overlays staging (epilogue)

    const int tid  = threadIdx.x;
    const int lane = tid & 31;
    const int warp = tid >> 5;
    const int wm = (warp >> 1) * 32;
    const int wn = (warp & 1) * 32;
    const int bid = blockIdx.x;
    const int m0  = (bid & 1) * 128;
    const int nsl = bid >> 1;
    const int n0  = nsl * 64;
    unsigned* bar = &g_barA[(bid & 1) * 16];

    for (int i = tid; i < 64 * 128; i += PTHREADS) {
        int n = i >> 7, k4 = (i & 127) * 4;
        *(uint4*)&smV[n * VSTR + k4] = *(const uint4*)&g_Vb[(size_t)(n0 + n) * 512 + k4];
    }

    float creg[4][2];
#pragma unroll
    for (int it = 0; it < 4; it++) {
        int idx = tid + it * PTHREADS;
        int lr = idx >> 3, jp = idx & 7;
        float2 cv = *(const float2*)&g_c[(m0 + lr) * HIDN + nsl * 16 + jp * 2];
        creg[it][0] = cv.x; creg[it][1] = cv.y;
    }

    const uint32_t smA_u = smem_u32(smA);
    const uint32_t smV_u = smem_u32(smV);

    uint32_t aoff[2];
#pragma unroll
    for (int mt = 0; mt < 2; mt++)
        aoff[mt] = (uint32_t)(wm + mt * 16 + (lane & 7) + ((lane >> 3) & 1) * 8) * ASTR
                 + ((lane >> 4) & 1) * 4;
    uint32_t voff[2];
#pragma unroll
    for (int p = 0; p < 2; p++)
        voff[p] = (uint32_t)(wn + p * 16 + (lane & 7) + ((lane >> 4) & 1) * 8) * VSTR
                + ((lane >> 3) & 1) * 4;

    // cp.async staging map: 128 rows x 8 16B-blocks = 1024 units / 256 thr = 4 each
    uint32_t hsrc_off[4];   // u32 offset within h half (row*512 + cb*4)
    uint32_t hdst_off[4];   // byte offset within a stage
#pragma unroll
    for (int i = 0; i < 4; i++) {
        int idx = tid + i * 256;
        int row = idx >> 3, cb = idx & 7;
        hsrc_off[i] = (uint32_t)row * 512 + cb * 4;
        hdst_off[i] = (uint32_t)(row * ASTR + cb * 4) * 4;
    }

    // Zin prefetch thread mapping (it-invariant jp)
    const int zlr0 = tid >> 3, zjp = tid & 7;

    // prefetch Zin for step 0
    uint4 zpre[4];
#pragma unroll
    for (int it = 0; it < 4; it++) {
        size_t zb = ((size_t)(m0 + zlr0 + it * 32)) * (NG / 2) + (n0 >> 1) + zjp * 4;
        zpre[it] = *(const uint4*)&g_Zinb[zb];
    }
    __syncthreads();

    for (int t = 0; t < SEQL; t++) {
        const unsigned* hin = g_hb[t & 1] + (size_t)m0 * 512;

        float acc[2][4][4];
#pragma unroll
        for (int a = 0; a < 2; a++)
#pragma unroll
            for (int b_ = 0; b_ < 4; b_++)
#pragma unroll
                for (int c_ = 0; c_ < 4; c_++) acc[a][b_][c_] = 0.f;

        // cp.async 3-stage pipeline over 16 K-chunks (32 half2 each)
        auto issue = [&](int chunk, int stage) {
            uint32_t base = smA_u + (uint32_t)stage * (STG_A * 4);
#pragma unroll
            for (int i = 0; i < 4; i++)
                CP_ASYNC16(base + hdst_off[i], hin + hsrc_off[i] + chunk * 32);
            CP_COMMIT();
        };

        issue(0, 0);
        issue(1, 1);

        int cur = 0, nxt = 2;
        for (int kc = 0; kc < 16; kc++) {
            CP_WAIT1();
            __syncthreads();

            const uint32_t abase = smA_u + (uint32_t)cur * (STG_A * 4);
            const uint32_t vbase = smV_u + (uint32_t)(kc * 32) * 4;
#pragma unroll
            for (int ks = 0; ks < 4; ks++) {
                unsigned af[2][4], bfr[4][2];
#pragma unroll
                for (int mtw = 0; mtw < 2; mtw++)
                    LDSM_X4(af[mtw][0], af[mtw][1], af[mtw][2], af[mtw][3],
                            abase + (aoff[mtw] + ks * 8) * 4);
#pragma unroll
                for (int p = 0; p < 2; p++)
                    LDSM_X4(bfr[2 * p][0], bfr[2 * p][1], bfr[2 * p + 1][0], bfr[2 * p + 1][1],
                            vbase + (voff[p] + ks * 8) * 4);
#pragma unroll
                for (int mtw = 0; mtw < 2; mtw++)
#pragma unroll
                    for (int ntw = 0; ntw < 4; ntw++)
                        mma_bf16(acc[mtw][ntw], af[mtw], bfr[ntw]);
            }
            if (kc + 2 < 16) issue(kc + 2, nxt);
            else CP_COMMIT();    // keep group count aligned with CP_WAIT1 semantics
            cur = (cur == 2) ? 0 : cur + 1;
            nxt = (nxt == 2) ? 0 : nxt + 1;
        }
        __syncthreads();   // all mma reads done before G overlays stage buffers

        // accum -> smem gate tile
#pragma unroll
        for (int mtw = 0; mtw < 2; mtw++)
#pragma unroll
            for (int ntw = 0; ntw < 4; ntw++) {
                int lr = wm + mtw * 16 + (lane >> 2);
                int lc = wn + ntw * 8 + (lane & 3) * 2;
                smG[lr * GS + lc]           = acc[mtw][ntw][0];
                smG[lr * GS + lc + 1]       = acc[mtw][ntw][1];
                smG[(lr + 8) * GS + lc]     = acc[mtw][ntw][2];
                smG[(lr + 8) * GS + lc + 1] = acc[mtw][ntw][3];
            }
        __syncthreads();

        // fused LSTM cell (c in registers)
        unsigned* hbout = g_hb[(t & 1) ^ 1];
#pragma unroll
        for (int it = 0; it < 4; it++) {
            int lr = zlr0 + it * 32;
            int m = m0 + lr;
            float2 za  = unpack_bf2(zpre[it].x);
            float2 zb2 = unpack_bf2(zpre[it].y);
            float2 zc  = unpack_bf2(zpre[it].z);
            float2 zd  = unpack_bf2(zpre[it].w);
            const float* Gp = &smG[lr * GS + zjp * 8];

            float i0 = fsig(Gp[0] + za.x);
            float f0 = fsig(Gp[1] + za.y);
            float g0 = ftanh(Gp[2] + zb2.x);
            float o0 = fsig(Gp[3] + zb2.y);
            float i1 = fsig(Gp[4] + zc.x);
            float f1 = fsig(Gp[5] + zc.y);
            float g1 = ftanh(Gp[6] + zd.x);
            float o1 = fsig(Gp[7] + zd.y);

            float cn0 = f0 * creg[it][0] + i0 * g0;
            float cn1 = f1 * creg[it][1] + i1 * g1;
            creg[it][0] = cn0; creg[it][1] = cn1;

            float h0v = o0 * ftanh(cn0);
            float h1v = o1 * ftanh(cn1);
            hbout[m * 512 + nsl * 8 + zjp] = pack_bf2(h0v, h1v);
            if (t == SEQL - 1) {
                float2 hf; hf.x = h0v; hf.y = h1v;
                *(float2*)&g_h[0][m * HIDN + nsl * 16 + zjp * 2] = hf;
            }
        }

        if (t < SEQL - 1) {
            // EARLY arrive: h writes are visible after this sync; signal peers before
            // doing our own Zin prefetch (prefetch hides behind peers' spin).
            __syncthreads();
            if (tid == 0) {
                __threadfence();
                atomicAdd(bar, 1u);
            }
            // prefetch next step's Zin (static data; no ordering needed)
#pragma unroll
            for (int it = 0; it < 4; it++) {
                size_t zb = ((size_t)(t + 1) * BATCH + m0 + zlr0 + it * 32) * (NG / 2)
                          + (n0 >> 1) + zjp * 4;
                zpre[it] = *(const uint4*)&g_Zinb[zb];
            }
            if (tid == 0) {
                const unsigned target = 64u * (t + 1);
                unsigned v;
                do {
                    asm volatile("ld.acquire.gpu.u32 %0, [%1];"
                                 : "=r"(v) : "l"(bar) : "memory");
                } while (v < target);
            }
            __syncthreads();
        }
    }
}

// ---------------- tf32 output projection: out = h_final @ W^T + b ----------------
__global__ __launch_bounds__(128)
void out_gemm_kernel(const float* __restrict__ W,
                     const float* __restrict__ biasp,
                     float* __restrict__ Cout)
{
    const int tid  = threadIdx.x;
    const int lane = tid & 31;
    const int warp = tid >> 5;
    const int wm = (warp >> 1) * 64;
    const int wn = (warp & 1) * 32;
    const int n0 = blockIdx.x * BN;
    const int m0 = blockIdx.y * BM;

    __shared__ struct { float A[2][BM * AS]; float B[2][BN * BSS]; } sm;

    const float* Ain = g_h[0];
    const int kcol  = (tid & 3) * 4;
    const int ldrow = tid >> 2;

    const float* arp[4];
#pragma unroll
    for (int i = 0; i < 4; i++)
        arp[i] = Ain + (size_t)(m0 + ldrow + 32 * i) * HIDN + kcol;
    const float* brp[2];
#pragma unroll
    for (int i = 0; i < 2; i++)
        brp[i] = W + (size_t)(n0 + ldrow + 32 * i) * HIDN + kcol;

    float4 areg[4], breg[2];
    float acc[4][4][4];
#pragma unroll
    for (int a = 0; a < 4; a++)
#pragma unroll
        for (int b_ = 0; b_ < 4; b_++)
#pragma unroll
            for (int c_ = 0; c_ < 4; c_++) acc[a][b_][c_] = 0.f;

#pragma unroll
    for (int i = 0; i < 4; i++) areg[i] = *(const float4*)(arp[i]);
#pragma unroll
    for (int i = 0; i < 2; i++) breg[i] = *(const float4*)(brp[i]);
#pragma unroll
    for (int i = 0; i < 4; i++) {
        float4 v = areg[i];
        v.x = f2tf32(v.x); v.y = f2tf32(v.y); v.z = f2tf32(v.z); v.w = f2tf32(v.w);
        *(float4*)&sm.A[0][(ldrow + 32 * i) * AS + kcol] = v;
    }
#pragma unroll
    for (int i = 0; i < 2; i++) {
        float4 v = breg[i];
        v.x = f2tf32(v.x); v.y = f2tf32(v.y); v.z = f2tf32(v.z); v.w = f2tf32(v.w);
        *(float4*)&sm.B[0][(ldrow + 32 * i) * BSS + kcol] = v;
    }
    __syncthreads();

    const int NCH = HIDN / BK;
    for (int kc = 0; kc < NCH; kc++) {
        int cur = kc & 1;
        if (kc + 1 < NCH) {
#pragma unroll
            for (int i = 0; i < 4; i++) areg[i] = *(const float4*)(arp[i] + (kc + 1) * BK);
#pragma unroll
            for (int i = 0; i < 2; i++) breg[i] = *(const float4*)(brp[i] + (kc + 1) * BK);
        }
#pragma unroll
        for (int k8 = 0; k8 < BK; k8 += 8) {
            uint32_t af[4][4], bfr[4][2];
#pragma unroll
            for (int mt = 0; mt < 4; mt++) {
                const float* ap = &sm.A[cur][(wm + mt * 16 + (lane >> 2)) * AS + k8 + (lane & 3)];
                af[mt][0] = __float_as_uint(ap[0]);
                af[mt][1] = __float_as_uint(ap[8 * AS]);
                af[mt][2] = __float_as_uint(ap[4]);
                af[mt][3] = __float_as_uint(ap[8 * AS + 4]);
            }
#pragma unroll
            for (int nt = 0; nt < 4; nt++) {
                const float* bp = &sm.B[cur][(wn + nt * 8 + (lane >> 2)) * BSS + k8 + (lane & 3)];
                bfr[nt][0] = __float_as_uint(bp[0]);
                bfr[nt][1] = __float_as_uint(bp[4]);
            }
#pragma unroll
            for (int mt = 0; mt < 4; mt++)
#pragma unroll
                for (int nt = 0; nt < 4; nt++)
                    asm volatile(
                        "mma.sync.aligned.m16n8k8.row.col.f32.tf32.tf32.f32 "
                        "{%0,%1,%2,%3}, {%4,%5,%6,%7}, {%8,%9}, {%0,%1,%2,%3};"
                        : "+f"(acc[mt][nt][0]), "+f"(acc[mt][nt][1]),
                          "+f"(acc[mt][nt][2]), "+f"(acc[mt][nt][3])
                        : "r"(af[mt][0]), "r"(af[mt][1]), "r"(af[mt][2]), "r"(af[mt][3]),
                          "r"(bfr[nt][0]), "r"(bfr[nt][1]));
        }
        if (kc + 1 < NCH) {
            int nxt = cur ^ 1;
#pragma unroll
            for (int i = 0; i < 4; i++) {
                float4 v = areg[i];
                v.x = f2tf32(v.x); v.y = f2tf32(v.y); v.z = f2tf32(v.z); v.w = f2tf32(v.w);
                *(float4*)&sm.A[nxt][(ldrow + 32 * i) * AS + kcol] = v;
            }
#pragma unroll
            for (int i = 0; i < 2; i++) {
                float4 v = breg[i];
                v.x = f2tf32(v.x); v.y = f2tf32(v.y); v.z = f2tf32(v.z); v.w = f2tf32(v.w);
                *(float4*)&sm.B[nxt][(ldrow + 32 * i) * BSS + kcol] = v;
            }
        }
        __syncthreads();
    }

#pragma unroll
    for (int mt = 0; mt < 4; mt++) {
#pragma unroll
        for (int nt = 0; nt < 4; nt++) {
            int r = m0 + wm + mt * 16 + (lane >> 2);
            int cidx = n0 + wn + nt * 8 + (lane & 3) * 2;
            float2 bv = *(const float2*)&biasp[cidx];
            float2 v0; v0.x = acc[mt][nt][0] + bv.x; v0.y = acc[mt][nt][1] + bv.y;
            float2 v1; v1.x = acc[mt][nt][2] + bv.x; v1.y = acc[mt][nt][3] + bv.y;
            *(float2*)&Cout[(size_t)r * NCLS + cidx] = v0;
            *(float2*)&Cout[(size_t)(r + 8) * NCLS + cidx] = v1;
        }
    }
}

// ---------------- launch ----------------
extern "C" void kernel_launch(void* const* d_in, const int* in_sizes, int n_in,
                              void* d_out, int out_size)
{
    const int*   X   = (const int*)  d_in[0];
    const float* h0  = (const float*)d_in[1];
    const float* c0  = (const float*)d_in[2];
    const float* emb = (const float*)d_in[3];
    const float* Ui  = (const float*)d_in[4];
    const float* Vi  = (const float*)d_in[5];
    const float* bi  = (const float*)d_in[6];
    const float* Uf  = (const float*)d_in[7];
    const float* Vf  = (const float*)d_in[8];
    const float* bf  = (const float*)d_in[9];
    const float* Uc  = (const float*)d_in[10];
    const float* Vc  = (const float*)d_in[11];
    const float* bc  = (const float*)d_in[12];
    const float* Uo  = (const float*)d_in[13];
    const float* Vo  = (const float*)d_in[14];
    const float* bo  = (const float*)d_in[15];
    const float* W   = (const float*)d_in[16];
    const float* b   = (const float*)d_in[17];
    float* out = (float*)d_out;

    cudaFuncSetAttribute(lstm_persistent_kernel,
                         cudaFuncAttributeMaxDynamicSharedMemorySize, SMEM_P_BYTES);
    cudaFuncSetAttribute(input_gemm_kernel,
                         cudaFuncAttributeMaxDynamicSharedMemorySize, IG_SMEM_B);

    // 1) pack weights (bf16 interleaved), biases, init state, reset barriers
    pack_kernel<<<(NG * (HIDN / 2) + 255) / 256, 256>>>(Ui, Vi, bi, Uf, Vf, bf,
                                                        Uc, Vc, bc, Uo, Vo, bo, h0, c0);
    pack_emb_kernel<<<(int)(((size_t)NCLS * (EMBD / 2) + 255) / 256), 256>>>(emb);

    // 2) all input-side gate preactivations (cp.async 3-stage, ldmatrix, bf16 Zin)
    input_gemm_kernel<<<dim3(NG / 128, (SEQL * BATCH) / 128), 256, IG_SMEM_B>>>(X);

    // 3) all 128 recurrent steps (V resident, cp.async h staging, early barrier arrive)
    lstm_persistent_kernel<<<NCTA, PTHREADS, SMEM_P_BYTES>>>();

    // 4) output projection (tf32): out = h_final @ W^T + b
    out_gemm_kernel<<<dim3(NCLS / BN, BATCH / BM), 128>>>(W, b, out);
}